// round 8
// baseline (speedup 1.0000x reference)
#include <cuda_runtime.h>
#include <cuda_bf16.h>
#include <math.h>
#include <stdint.h>

#define BSZ 32
#define SEQL 2048
#define INF 512
#define HID 256
#define MTOT (BSZ * SEQL)           // 65536 rows
#define XXN (BSZ * SEQL * 2 * HID)  // 33554432
#define HOUTN (4 * BSZ * HID)       // 32768

// ---------------- scratch (static device globals; no allocation) -------------
__device__ __nv_bfloat16 g_xhi [MTOT * INF];
__device__ __nv_bfloat16 g_xlo [MTOT * INF];
__device__ __nv_bfloat16 g_Wfc3[HID * 3 * INF];       // [Whi|Whi|Wlo] along k'
__device__ __nv_bfloat16 g_W23 [2 * HID * 3 * HID];
__device__ __nv_bfloat16 g_Hhi [MTOT * HID];
__device__ __nv_bfloat16 g_Hlo [MTOT * HID];
__device__ float         g_G1  [MTOT * HID];
__device__ __nv_bfloat16 g_Ylhi[MTOT * HID];
__device__ __nv_bfloat16 g_Yllo[MTOT * HID];
__device__ __nv_bfloat16 g_Yrhi[MTOT * HID];
__device__ __nv_bfloat16 g_Yrlo[MTOT * HID];
__device__ float         g_Ga  [MTOT * HID];
__device__ float         g_Gb  [MTOT * HID];
__device__ float         g_hdump[4 * BSZ * HID];

#define K2LOG2E 2.8853900817779268f   // 2*log2(e)

// ---------------- fast math ----------------
__device__ __forceinline__ float fast_ex2(float x) {
    float y; asm("ex2.approx.f32 %0, %1;" : "=f"(y) : "f"(x)); return y;
}
__device__ __forceinline__ float fast_rcp(float x) {
    float y; asm("rcp.approx.f32 %0, %1;" : "=f"(y) : "f"(x)); return y;
}
__device__ __forceinline__ float fast_sigmoid(float z) {
    return fast_rcp(1.0f + fast_ex2(-1.4426950408889634f * z));
}
__device__ __forceinline__ void split_bf16(float v, __nv_bfloat16& hi, __nv_bfloat16& lo) {
    hi = __float2bfloat16(v);
    lo = __float2bfloat16(v - __bfloat162float(hi));
}

// ---------------- PTX helpers ----------------
__device__ __forceinline__ void ldsm4(uint32_t (&r)[4], uint32_t saddr) {
    asm volatile("ldmatrix.sync.aligned.m8n8.x4.shared.b16 {%0,%1,%2,%3}, [%4];"
                 : "=r"(r[0]), "=r"(r[1]), "=r"(r[2]), "=r"(r[3]) : "r"(saddr));
}
__device__ __forceinline__ void mma16816(float (&d)[4], const uint32_t (&a)[4],
                                         uint32_t b0, uint32_t b1) {
    asm volatile("mma.sync.aligned.m16n8k16.row.col.f32.bf16.bf16.f32 "
                 "{%0,%1,%2,%3}, {%4,%5,%6,%7}, {%8,%9}, {%0,%1,%2,%3};"
                 : "+f"(d[0]), "+f"(d[1]), "+f"(d[2]), "+f"(d[3])
                 : "r"(a[0]), "r"(a[1]), "r"(a[2]), "r"(a[3]), "r"(b0), "r"(b1));
}
__device__ __forceinline__ void cpa16(uint32_t s, const void* g) {
    asm volatile("cp.async.cg.shared.global [%0], [%1], 16;" :: "r"(s), "l"(g));
}
__device__ __forceinline__ void cpa_commit() { asm volatile("cp.async.commit_group;"); }

// ---------------- conversion kernels ----------------
__global__ void convert_x_kernel(const float* __restrict__ x,
                                 __nv_bfloat16* __restrict__ xhi,
                                 __nv_bfloat16* __restrict__ xlo, int n4)
{
    int i = blockIdx.x * blockDim.x + threadIdx.x;
    if (i >= n4) return;
    float4 v = reinterpret_cast<const float4*>(x)[i];
    __nv_bfloat16 h0, l0, h1, l1, h2, l2, h3, l3;
    split_bf16(v.x, h0, l0); split_bf16(v.y, h1, l1);
    split_bf16(v.z, h2, l2); split_bf16(v.w, h3, l3);
    reinterpret_cast<__nv_bfloat162*>(xhi)[2 * i]     = __nv_bfloat162(h0, h1);
    reinterpret_cast<__nv_bfloat162*>(xhi)[2 * i + 1] = __nv_bfloat162(h2, h3);
    reinterpret_cast<__nv_bfloat162*>(xlo)[2 * i]     = __nv_bfloat162(l0, l1);
    reinterpret_cast<__nv_bfloat162*>(xlo)[2 * i + 1] = __nv_bfloat162(l2, l3);
}

// Build W' = [Whi | Whi | Wlo] (k' = 3K) for W_fc and both W2 layers.
__global__ void convert_w_kernel(const float* __restrict__ Wfc,
                                 const float* __restrict__ W2,
                                 __nv_bfloat16* __restrict__ Wfc3,
                                 __nv_bfloat16* __restrict__ W23)
{
    int i = blockIdx.x * blockDim.x + threadIdx.x;
    const int t1 = HID * INF;
    const int t2 = 2 * HID * HID;
    if (i < t1) {
        int n = i / INF, k = i % INF;
        __nv_bfloat16 hi, lo; split_bf16(Wfc[i], hi, lo);
        __nv_bfloat16* base = Wfc3 + (size_t)n * (3 * INF);
        base[k] = hi; base[INF + k] = hi; base[2 * INF + k] = lo;
    } else if (i < t1 + t2) {
        int j = i - t1;
        int l = j / (HID * HID); int r = j % (HID * HID);
        int n = r / HID, k = r % HID;
        __nv_bfloat16 hi, lo; split_bf16(W2[j], hi, lo);
        __nv_bfloat16* base = W23 + (size_t)l * HID * (3 * HID) + (size_t)n * (3 * HID);
        base[k] = hi; base[HID + k] = hi; base[2 * HID + k] = lo;
    }
}

// ---------------- tensor-core GEMM -------------------------------------------
// Block tile 128x64, 8 warps (32x32 each), k-chunk 32, 3-stage cp.async
// circular pipeline, ONE __syncthreads per chunk, ldsm/mma fragment
// double-buffering (smem loads for the next half-chunk overlap current MMAs).
// Grid: (N/64, M/128, nz) — bn fastest so same-M blocks co-run and share A in L2.
// OUT=0: C = A@W'^T + bias -> split bf16 planes Chi/Clo.
// OUT=1: g = sigmoid(acc + bias) -> fp32 G plane.
// blockIdx.z == 1 selects the second (A2 -> Gb) problem (fused layer-2 gates).
#define A_STRIDE 40
#define A_TILE (128 * A_STRIDE)
#define W_TILE (64 * A_STRIDE)
#define NSTG 3

template <int OUT>
__global__ __launch_bounds__(256, 2)
void gemm_tc(const __nv_bfloat16* __restrict__ Ahi_, const __nv_bfloat16* __restrict__ Alo_,
             const __nv_bfloat16* __restrict__ Ahi2, const __nv_bfloat16* __restrict__ Alo2,
             const __nv_bfloat16* __restrict__ W3, const float* __restrict__ bias,
             float* __restrict__ Ga, float* __restrict__ Gb,
             __nv_bfloat16* __restrict__ Chi, __nv_bfloat16* __restrict__ Clo, int K)
{
    __shared__ __nv_bfloat16 As[NSTG][A_TILE];
    __shared__ __nv_bfloat16 Ws[NSTG][W_TILE];

    const __nv_bfloat16* Ahi = (blockIdx.z == 0) ? Ahi_ : Ahi2;
    const __nv_bfloat16* Alo = (blockIdx.z == 0) ? Alo_ : Alo2;
    float* G = (blockIdx.z == 0) ? Ga : Gb;

    const int tid  = threadIdx.x;
    const int bm   = blockIdx.y * 128;
    const int bn   = blockIdx.x * 64;
    const int warp = tid >> 5;
    const int lane = tid & 31;
    const int K3   = 3 * K;
    const int n1   = K >> 5;
    const int nc   = 3 * n1;

    const uint32_t sA = (uint32_t)__cvta_generic_to_shared(&As[0][0]);
    const uint32_t sW = (uint32_t)__cvta_generic_to_shared(&Ws[0][0]);

    const int ar0 = tid >> 2, ar1 = (tid + 256) >> 2;
    const int ac  = (tid & 3) * 8;
    const int wr  = tid >> 2;
    const uint32_t sAoff0 = (uint32_t)(ar0 * A_STRIDE + ac) * 2;
    const uint32_t sAoff1 = (uint32_t)(ar1 * A_STRIDE + ac) * 2;
    const uint32_t sWoff  = (uint32_t)(wr  * A_STRIDE + ac) * 2;
    const __nv_bfloat16* Wg = W3 + (size_t)(bn + wr) * K3 + ac;

    float acc[2][4][4];
#pragma unroll
    for (int a = 0; a < 2; a++)
#pragma unroll
        for (int b = 0; b < 4; b++)
#pragma unroll
            for (int c = 0; c < 4; c++) acc[a][b][c] = 0.0f;

    auto prefetch = [&](int c, int buf) {
        const __nv_bfloat16* Aseg; int kk;
        if (c < n1)           { Aseg = Ahi; kk = c; }
        else if (c < 2 * n1)  { Aseg = Alo; kk = c - n1; }
        else                  { Aseg = Ahi; kk = c - 2 * n1; }
        const __nv_bfloat16* Abase = Aseg + (size_t)bm * K + kk * 32 + ac;
        cpa16(sA + buf * (A_TILE * 2) + sAoff0, Abase + (size_t)ar0 * K);
        cpa16(sA + buf * (A_TILE * 2) + sAoff1, Abase + (size_t)ar1 * K);
        cpa16(sW + buf * (W_TILE * 2) + sWoff,  Wg + c * 32);
    };

    const int wm = warp & 3;
    const int wn = warp >> 2;
    const int aRow = wm * 32 + (lane & 15);
    const int aColB = (lane >> 4) * 8;
    const int bRow = wn * 32 + (lane & 7) + ((lane >> 4) & 1) * 8;
    const int bColB = ((lane >> 3) & 1) * 8;

    // fragment double buffer (slot = ks parity)
    uint32_t afr[2][2][4], bfr[2][2][4];

    auto load_frags = [&](int buf, int ks, int slot) {
        const uint32_t aBase = sA + buf * (A_TILE * 2);
        const uint32_t wBase = sW + buf * (W_TILE * 2);
#pragma unroll
        for (int mi = 0; mi < 2; mi++)
            ldsm4(afr[slot][mi], aBase + (uint32_t)((aRow + mi * 16) * A_STRIDE
                                                    + ks * 16 + aColB) * 2);
#pragma unroll
        for (int bi = 0; bi < 2; bi++)
            ldsm4(bfr[slot][bi], wBase + (uint32_t)((bRow + bi * 16) * A_STRIDE
                                                    + ks * 16 + bColB) * 2);
    };
    auto do_mma = [&](int slot) {
#pragma unroll
        for (int mi = 0; mi < 2; mi++) {
            mma16816(acc[mi][0], afr[slot][mi], bfr[slot][0][0], bfr[slot][0][1]);
            mma16816(acc[mi][1], afr[slot][mi], bfr[slot][0][2], bfr[slot][0][3]);
            mma16816(acc[mi][2], afr[slot][mi], bfr[slot][1][0], bfr[slot][1][1]);
            mma16816(acc[mi][3], afr[slot][mi], bfr[slot][1][2], bfr[slot][1][3]);
        }
    };

    // prologue: 2 stages in flight, buf0 ready, preload its ks=0 frags
    prefetch(0, 0); cpa_commit();
    prefetch(1, 1); cpa_commit();
    asm volatile("cp.async.wait_group 1;");
    __syncthreads();
    load_frags(0, 0, 0);

    int buf = 0;
    for (int c = 0; c < nc; c++) {
        load_frags(buf, 1, 1);           // ks=1 frags (overlaps mma below)
        do_mma(0);                        // ks=0
        if (c + 2 < nc) {
            int pf = buf + 2; if (pf >= NSTG) pf -= NSTG;
            prefetch(c + 2, pf);
            cpa_commit();
            asm volatile("cp.async.wait_group 1;");
        } else {
            asm volatile("cp.async.wait_group 0;");
        }
        __syncthreads();                  // buf[c+1] visible to all
        const int nbuf = (buf + 1 == NSTG) ? 0 : buf + 1;
        if (c + 1 < nc) load_frags(nbuf, 0, 0);  // next chunk ks=0 (overlaps mma)
        do_mma(1);                        // ks=1
        buf = nbuf;
    }

    // epilogue
#pragma unroll
    for (int mi = 0; mi < 2; mi++) {
#pragma unroll
        for (int ni = 0; ni < 4; ni++) {
            const int m0 = bm + wm * 32 + mi * 16 + (lane >> 2);
            const int n0 = bn + wn * 32 + ni * 8 + (lane & 3) * 2;
            const float b0 = bias[n0], b1 = bias[n0 + 1];
            float v00 = acc[mi][ni][0] + b0, v01 = acc[mi][ni][1] + b1;
            float v10 = acc[mi][ni][2] + b0, v11 = acc[mi][ni][3] + b1;
            if (OUT == 1) {
                v00 = fast_sigmoid(v00); v01 = fast_sigmoid(v01);
                v10 = fast_sigmoid(v10); v11 = fast_sigmoid(v11);
                *reinterpret_cast<float2*>(G + (size_t)m0 * HID + n0)       = make_float2(v00, v01);
                *reinterpret_cast<float2*>(G + (size_t)(m0 + 8) * HID + n0) = make_float2(v10, v11);
            } else {
                __nv_bfloat16 h0, l0, h1, l1;
                split_bf16(v00, h0, l0); split_bf16(v01, h1, l1);
                *reinterpret_cast<__nv_bfloat162*>(Chi + (size_t)m0 * HID + n0) = __nv_bfloat162(h0, h1);
                *reinterpret_cast<__nv_bfloat162*>(Clo + (size_t)m0 * HID + n0) = __nv_bfloat162(l0, l1);
                split_bf16(v10, h0, l0); split_bf16(v11, h1, l1);
                *reinterpret_cast<__nv_bfloat162*>(Chi + (size_t)(m0 + 8) * HID + n0) = __nv_bfloat162(h0, h1);
                *reinterpret_cast<__nv_bfloat162*>(Clo + (size_t)(m0 + 8) * HID + n0) = __nv_bfloat162(l0, l1);
            }
        }
    }
}

// ---------------- sequential scan (both directions in one launch) ------------
// Off-chain LOAD computes a = Kxg, c = Kx^2(1-g); chain per step is just
// v = a*h + c; t = ex2(v); h = 1 - 2*rcp(1+t)  (~44 cyc).
// OM=0: write split bf16 planes (layer-1 Y). OM=1: write fp32 into d_out.
#define SU 16
template <int OM>
__global__ __launch_bounds__(128)
void scan_tc(const __nv_bfloat16* __restrict__ xAhi, const __nv_bfloat16* __restrict__ xAlo,
             const float* __restrict__ gA,
             const __nv_bfloat16* __restrict__ xBhi, const __nv_bfloat16* __restrict__ xBlo,
             const float* __restrict__ gB,
             __nv_bfloat16* __restrict__ yAhi, __nv_bfloat16* __restrict__ yAlo,
             __nv_bfloat16* __restrict__ yBhi, __nv_bfloat16* __restrict__ yBlo,
             float* __restrict__ outF,
             float* __restrict__ hA, float* __restrict__ hB)
{
    const int gid = blockIdx.x * 128 + threadIdx.x;  // 0..16383
    const int dir = gid >> 13;
    const int id  = gid & 8191;
    const int b = id >> 8;
    const int j = id & 255;

    const __nv_bfloat16 *xh, *xl;
    const float* gp;
    __nv_bfloat16 *yh, *yl;
    float* hp;
    int t0, dt;
    if (dir == 0) { xh = xAhi; xl = xAlo; gp = gA; yh = yAhi; yl = yAlo;
                    hp = hA; t0 = 0;        dt =  1; }
    else          { xh = xBhi; xl = xBlo; gp = gB; yh = yBhi; yl = yBlo;
                    hp = hB; t0 = SEQL - 1; dt = -1; }

    const int base = b * SEQL * HID + j;
    const size_t obase = (size_t)b * SEQL * (2 * HID) + (size_t)dir * HID + j;

    float aa[2][SU], cc[2][SU];

    auto LOAD = [&](int s0, int bufi) {
#pragma unroll
        for (int u = 0; u < SU; u++) {
            const int t = t0 + dt * (s0 + u);
            const int idx = base + t * HID;
            const float xv = __bfloat162float(__ldg(xh + idx))
                           + __bfloat162float(__ldg(xl + idx));
            const float g  = __ldg(gp + idx);
            aa[bufi][u] = K2LOG2E * xv * g;
            cc[bufi][u] = K2LOG2E * xv * xv * (1.0f - g);
        }
    };

    LOAD(0, 0);
    float h = 0.0f;
    int cur = 0;
    for (int s0 = 0; s0 < SEQL; s0 += SU) {
        const bool more = (s0 + SU) < SEQL;
        if (more) LOAD(s0 + SU, cur ^ 1);
#pragma unroll
        for (int u = 0; u < SU; u++) {
            const float v = fmaf(aa[cur][u], h, cc[cur][u]);
            const float t = fast_ex2(v);
            h = fmaf(-2.0f, fast_rcp(t + 1.0f), 1.0f);
            const int tt = t0 + dt * (s0 + u);
            if (OM == 0) {
                __nv_bfloat16 hi, lo; split_bf16(h, hi, lo);
                yh[base + tt * HID] = hi;
                yl[base + tt * HID] = lo;
            } else {
                outF[obase + (size_t)tt * (2 * HID)] = h;
            }
        }
        cur ^= 1;
    }
    hp[(b << 8) + j] = h;
}

// ---------------- launch ----------------
extern "C" void kernel_launch(void* const* d_in, const int* in_sizes, int n_in,
                              void* d_out, int out_size)
{
    const float* x    = (const float*)d_in[0];  // [32,2048,512]
    const float* W_fc = (const float*)d_in[1];  // [256,512]
    const float* b_fc = (const float*)d_in[2];  // [256]
    // d_in[3] (W1), d_in[4] (b1): mathematically dead (blending1 == identity)
    const float* W2   = (const float*)d_in[5];  // [2,256,256]
    const float* b2   = (const float*)d_in[6];  // [2,256]
    float* out = (float*)d_out;

    __nv_bfloat16 *xhi, *xlo, *Wfc3, *W23, *Hhi, *Hlo, *Ylhi, *Yllo, *Yrhi, *Yrlo;
    float *G1, *Ga, *Gb, *hd;
    cudaGetSymbolAddress((void**)&xhi,  g_xhi);
    cudaGetSymbolAddress((void**)&xlo,  g_xlo);
    cudaGetSymbolAddress((void**)&Wfc3, g_Wfc3);
    cudaGetSymbolAddress((void**)&W23,  g_W23);
    cudaGetSymbolAddress((void**)&Hhi,  g_Hhi);
    cudaGetSymbolAddress((void**)&Hlo,  g_Hlo);
    cudaGetSymbolAddress((void**)&G1,   g_G1);
    cudaGetSymbolAddress((void**)&Ylhi, g_Ylhi);
    cudaGetSymbolAddress((void**)&Yllo, g_Yllo);
    cudaGetSymbolAddress((void**)&Yrhi, g_Yrhi);
    cudaGetSymbolAddress((void**)&Yrlo, g_Yrlo);
    cudaGetSymbolAddress((void**)&Ga,   g_Ga);
    cudaGetSymbolAddress((void**)&Gb,   g_Gb);
    cudaGetSymbolAddress((void**)&hd,   g_hdump);

    float* hout = (out_size >= XXN + HOUTN) ? (out + XXN) : hd;

    // 0) operand conversion (x -> hi/lo planes; W -> [Whi|Whi|Wlo])
    {
        int n4 = MTOT * INF / 4;
        convert_x_kernel<<<(n4 + 255) / 256, 256>>>(x, xhi, xlo, n4);
        int nw = HID * INF + 2 * HID * HID;
        convert_w_kernel<<<(nw + 255) / 256, 256>>>(W_fc, W2, Wfc3, W23);
    }

    const dim3 blk(256);
    const dim3 grd1(HID / 64, MTOT / 128, 1);   // bn fastest -> A reuse in L2
    const dim3 grd2(HID / 64, MTOT / 128, 2);

    // 1) input projection -> split bf16 H planes
    gemm_tc<0><<<grd1, blk>>>(xhi, xlo, nullptr, nullptr, Wfc3, b_fc,
                              nullptr, nullptr, Hhi, Hlo, INF);
    // 2) layer-1 gates (shared by both directions) -> fp32 G1
    gemm_tc<1><<<grd1, blk>>>(Hhi, Hlo, nullptr, nullptr, W23, b2,
                              G1, nullptr, nullptr, nullptr, HID);
    // 3) layer-1 scans (fwd+rev in one launch) -> split Y planes + h_out[0,1]
    scan_tc<0><<<128, 128>>>(Hhi, Hlo, G1, Hhi, Hlo, G1,
                             Ylhi, Yllo, Yrhi, Yrlo,
                             nullptr, hout, hout + BSZ * HID);
    // 4) layer-2 gates, both directions fused via gridDim.z -> Ga, Gb
    gemm_tc<1><<<grd2, blk>>>(Ylhi, Yllo, Yrhi, Yrlo,
                              W23 + (size_t)HID * 3 * HID, b2 + HID,
                              Ga, Gb, nullptr, nullptr, HID);
    // 5) layer-2 scans write straight into d_out + h_out[2,3]
    scan_tc<1><<<128, 128>>>(Ylhi, Yllo, Ga, Yrhi, Yrlo, Gb,
                             nullptr, nullptr, nullptr, nullptr,
                             out, hout + 2 * BSZ * HID, hout + 3 * BSZ * HID);
}

// round 9
// speedup vs baseline: 1.1192x; 1.1192x over previous
#include <cuda_runtime.h>
#include <cuda_bf16.h>
#include <math.h>
#include <stdint.h>

#define BSZ 32
#define SEQL 2048
#define INF 512
#define HID 256
#define MTOT (BSZ * SEQL)           // 65536 rows
#define XXN (BSZ * SEQL * 2 * HID)  // 33554432
#define HOUTN (4 * BSZ * HID)       // 32768

// ---------------- scratch (static device globals; no allocation) -------------
__device__ __nv_bfloat16 g_xhi [MTOT * INF];
__device__ __nv_bfloat16 g_xlo [MTOT * INF];
__device__ __nv_bfloat16 g_Wfc3[HID * 3 * INF];       // [Whi|Whi|Wlo] along k'
__device__ __nv_bfloat16 g_W23 [2 * HID * 3 * HID];
__device__ __nv_bfloat16 g_Hhi [MTOT * HID];
__device__ __nv_bfloat16 g_Hlo [MTOT * HID];
__device__ float         g_G1  [MTOT * HID];
__device__ __nv_bfloat16 g_Ylhi[MTOT * HID];
__device__ __nv_bfloat16 g_Yllo[MTOT * HID];
__device__ __nv_bfloat16 g_Yrhi[MTOT * HID];
__device__ __nv_bfloat16 g_Yrlo[MTOT * HID];
__device__ float         g_Ga  [MTOT * HID];
__device__ float         g_Gb  [MTOT * HID];
__device__ float         g_hdump[4 * BSZ * HID];

#define K2LOG2E 2.8853900817779268f   // 2*log2(e)

// ---------------- fast math ----------------
__device__ __forceinline__ float fast_ex2(float x) {
    float y; asm("ex2.approx.f32 %0, %1;" : "=f"(y) : "f"(x)); return y;
}
__device__ __forceinline__ float fast_rcp(float x) {
    float y; asm("rcp.approx.f32 %0, %1;" : "=f"(y) : "f"(x)); return y;
}
__device__ __forceinline__ float fast_sigmoid(float z) {
    return fast_rcp(1.0f + fast_ex2(-1.4426950408889634f * z));
}
__device__ __forceinline__ void split_bf16(float v, __nv_bfloat16& hi, __nv_bfloat16& lo) {
    hi = __float2bfloat16(v);
    lo = __float2bfloat16(v - __bfloat162float(hi));
}

// ---------------- PTX helpers ----------------
__device__ __forceinline__ void ldsm4(uint32_t (&r)[4], uint32_t saddr) {
    asm volatile("ldmatrix.sync.aligned.m8n8.x4.shared.b16 {%0,%1,%2,%3}, [%4];"
                 : "=r"(r[0]), "=r"(r[1]), "=r"(r[2]), "=r"(r[3]) : "r"(saddr));
}
__device__ __forceinline__ void mma16816(float (&d)[4], const uint32_t (&a)[4],
                                         uint32_t b0, uint32_t b1) {
    asm volatile("mma.sync.aligned.m16n8k16.row.col.f32.bf16.bf16.f32 "
                 "{%0,%1,%2,%3}, {%4,%5,%6,%7}, {%8,%9}, {%0,%1,%2,%3};"
                 : "+f"(d[0]), "+f"(d[1]), "+f"(d[2]), "+f"(d[3])
                 : "r"(a[0]), "r"(a[1]), "r"(a[2]), "r"(a[3]), "r"(b0), "r"(b1));
}
__device__ __forceinline__ void cpa16(uint32_t s, const void* g) {
    asm volatile("cp.async.cg.shared.global [%0], [%1], 16;" :: "r"(s), "l"(g));
}
__device__ __forceinline__ void cpa_commit() { asm volatile("cp.async.commit_group;"); }

// ---------------- conversion kernels ----------------
__global__ void convert_x_kernel(const float* __restrict__ x,
                                 __nv_bfloat16* __restrict__ xhi,
                                 __nv_bfloat16* __restrict__ xlo, int n4)
{
    int i = blockIdx.x * blockDim.x + threadIdx.x;
    if (i >= n4) return;
    float4 v = reinterpret_cast<const float4*>(x)[i];
    __nv_bfloat16 h0, l0, h1, l1, h2, l2, h3, l3;
    split_bf16(v.x, h0, l0); split_bf16(v.y, h1, l1);
    split_bf16(v.z, h2, l2); split_bf16(v.w, h3, l3);
    reinterpret_cast<__nv_bfloat162*>(xhi)[2 * i]     = __nv_bfloat162(h0, h1);
    reinterpret_cast<__nv_bfloat162*>(xhi)[2 * i + 1] = __nv_bfloat162(h2, h3);
    reinterpret_cast<__nv_bfloat162*>(xlo)[2 * i]     = __nv_bfloat162(l0, l1);
    reinterpret_cast<__nv_bfloat162*>(xlo)[2 * i + 1] = __nv_bfloat162(l2, l3);
}

// Build W' = [Whi | Whi | Wlo] (k' = 3K) for W_fc and both W2 layers.
__global__ void convert_w_kernel(const float* __restrict__ Wfc,
                                 const float* __restrict__ W2,
                                 __nv_bfloat16* __restrict__ Wfc3,
                                 __nv_bfloat16* __restrict__ W23)
{
    int i = blockIdx.x * blockDim.x + threadIdx.x;
    const int t1 = HID * INF;
    const int t2 = 2 * HID * HID;
    if (i < t1) {
        int n = i / INF, k = i % INF;
        __nv_bfloat16 hi, lo; split_bf16(Wfc[i], hi, lo);
        __nv_bfloat16* base = Wfc3 + (size_t)n * (3 * INF);
        base[k] = hi; base[INF + k] = hi; base[2 * INF + k] = lo;
    } else if (i < t1 + t2) {
        int j = i - t1;
        int l = j / (HID * HID); int r = j % (HID * HID);
        int n = r / HID, k = r % HID;
        __nv_bfloat16 hi, lo; split_bf16(W2[j], hi, lo);
        __nv_bfloat16* base = W23 + (size_t)l * HID * (3 * HID) + (size_t)n * (3 * HID);
        base[k] = hi; base[HID + k] = hi; base[2 * HID + k] = lo;
    }
}

// ---------------- tensor-core GEMM (unchanged from R8 — proven faster) -------
// Block tile 128x64, 8 warps (32x32 each), k-chunk 32, 3-stage cp.async
// circular pipeline, ONE __syncthreads per chunk, ldsm/mma fragment
// double-buffering. Grid: (N/64, M/128, nz) — bn fastest for A reuse in L2.
// OUT=0: C = A@W'^T + bias -> split bf16 planes Chi/Clo.
// OUT=1: g = sigmoid(acc + bias) -> fp32 G plane.
#define A_STRIDE 40
#define A_TILE (128 * A_STRIDE)
#define W_TILE (64 * A_STRIDE)
#define NSTG 3

template <int OUT>
__global__ __launch_bounds__(256, 2)
void gemm_tc(const __nv_bfloat16* __restrict__ Ahi_, const __nv_bfloat16* __restrict__ Alo_,
             const __nv_bfloat16* __restrict__ Ahi2, const __nv_bfloat16* __restrict__ Alo2,
             const __nv_bfloat16* __restrict__ W3, const float* __restrict__ bias,
             float* __restrict__ Ga, float* __restrict__ Gb,
             __nv_bfloat16* __restrict__ Chi, __nv_bfloat16* __restrict__ Clo, int K)
{
    __shared__ __nv_bfloat16 As[NSTG][A_TILE];
    __shared__ __nv_bfloat16 Ws[NSTG][W_TILE];

    const __nv_bfloat16* Ahi = (blockIdx.z == 0) ? Ahi_ : Ahi2;
    const __nv_bfloat16* Alo = (blockIdx.z == 0) ? Alo_ : Alo2;
    float* G = (blockIdx.z == 0) ? Ga : Gb;

    const int tid  = threadIdx.x;
    const int bm   = blockIdx.y * 128;
    const int bn   = blockIdx.x * 64;
    const int warp = tid >> 5;
    const int lane = tid & 31;
    const int K3   = 3 * K;
    const int n1   = K >> 5;
    const int nc   = 3 * n1;

    const uint32_t sA = (uint32_t)__cvta_generic_to_shared(&As[0][0]);
    const uint32_t sW = (uint32_t)__cvta_generic_to_shared(&Ws[0][0]);

    const int ar0 = tid >> 2, ar1 = (tid + 256) >> 2;
    const int ac  = (tid & 3) * 8;
    const int wr  = tid >> 2;
    const uint32_t sAoff0 = (uint32_t)(ar0 * A_STRIDE + ac) * 2;
    const uint32_t sAoff1 = (uint32_t)(ar1 * A_STRIDE + ac) * 2;
    const uint32_t sWoff  = (uint32_t)(wr  * A_STRIDE + ac) * 2;
    const __nv_bfloat16* Wg = W3 + (size_t)(bn + wr) * K3 + ac;

    float acc[2][4][4];
#pragma unroll
    for (int a = 0; a < 2; a++)
#pragma unroll
        for (int b = 0; b < 4; b++)
#pragma unroll
            for (int c = 0; c < 4; c++) acc[a][b][c] = 0.0f;

    auto prefetch = [&](int c, int buf) {
        const __nv_bfloat16* Aseg; int kk;
        if (c < n1)           { Aseg = Ahi; kk = c; }
        else if (c < 2 * n1)  { Aseg = Alo; kk = c - n1; }
        else                  { Aseg = Ahi; kk = c - 2 * n1; }
        const __nv_bfloat16* Abase = Aseg + (size_t)bm * K + kk * 32 + ac;
        cpa16(sA + buf * (A_TILE * 2) + sAoff0, Abase + (size_t)ar0 * K);
        cpa16(sA + buf * (A_TILE * 2) + sAoff1, Abase + (size_t)ar1 * K);
        cpa16(sW + buf * (W_TILE * 2) + sWoff,  Wg + c * 32);
    };

    const int wm = warp & 3;
    const int wn = warp >> 2;
    const int aRow = wm * 32 + (lane & 15);
    const int aColB = (lane >> 4) * 8;
    const int bRow = wn * 32 + (lane & 7) + ((lane >> 4) & 1) * 8;
    const int bColB = ((lane >> 3) & 1) * 8;

    uint32_t afr[2][2][4], bfr[2][2][4];

    auto load_frags = [&](int buf, int ks, int slot) {
        const uint32_t aBase = sA + buf * (A_TILE * 2);
        const uint32_t wBase = sW + buf * (W_TILE * 2);
#pragma unroll
        for (int mi = 0; mi < 2; mi++)
            ldsm4(afr[slot][mi], aBase + (uint32_t)((aRow + mi * 16) * A_STRIDE
                                                    + ks * 16 + aColB) * 2);
#pragma unroll
        for (int bi = 0; bi < 2; bi++)
            ldsm4(bfr[slot][bi], wBase + (uint32_t)((bRow + bi * 16) * A_STRIDE
                                                    + ks * 16 + bColB) * 2);
    };
    auto do_mma = [&](int slot) {
#pragma unroll
        for (int mi = 0; mi < 2; mi++) {
            mma16816(acc[mi][0], afr[slot][mi], bfr[slot][0][0], bfr[slot][0][1]);
            mma16816(acc[mi][1], afr[slot][mi], bfr[slot][0][2], bfr[slot][0][3]);
            mma16816(acc[mi][2], afr[slot][mi], bfr[slot][1][0], bfr[slot][1][1]);
            mma16816(acc[mi][3], afr[slot][mi], bfr[slot][1][2], bfr[slot][1][3]);
        }
    };

    prefetch(0, 0); cpa_commit();
    prefetch(1, 1); cpa_commit();
    asm volatile("cp.async.wait_group 1;");
    __syncthreads();
    load_frags(0, 0, 0);

    int buf = 0;
    for (int c = 0; c < nc; c++) {
        load_frags(buf, 1, 1);
        do_mma(0);
        if (c + 2 < nc) {
            int pf = buf + 2; if (pf >= NSTG) pf -= NSTG;
            prefetch(c + 2, pf);
            cpa_commit();
            asm volatile("cp.async.wait_group 1;");
        } else {
            asm volatile("cp.async.wait_group 0;");
        }
        __syncthreads();
        const int nbuf = (buf + 1 == NSTG) ? 0 : buf + 1;
        if (c + 1 < nc) load_frags(nbuf, 0, 0);
        do_mma(1);
        buf = nbuf;
    }

    // epilogue
#pragma unroll
    for (int mi = 0; mi < 2; mi++) {
#pragma unroll
        for (int ni = 0; ni < 4; ni++) {
            const int m0 = bm + wm * 32 + mi * 16 + (lane >> 2);
            const int n0 = bn + wn * 32 + ni * 8 + (lane & 3) * 2;
            const float b0 = bias[n0], b1 = bias[n0 + 1];
            float v00 = acc[mi][ni][0] + b0, v01 = acc[mi][ni][1] + b1;
            float v10 = acc[mi][ni][2] + b0, v11 = acc[mi][ni][3] + b1;
            if (OUT == 1) {
                v00 = fast_sigmoid(v00); v01 = fast_sigmoid(v01);
                v10 = fast_sigmoid(v10); v11 = fast_sigmoid(v11);
                *reinterpret_cast<float2*>(G + (size_t)m0 * HID + n0)       = make_float2(v00, v01);
                *reinterpret_cast<float2*>(G + (size_t)(m0 + 8) * HID + n0) = make_float2(v10, v11);
            } else {
                __nv_bfloat16 h0, l0, h1, l1;
                split_bf16(v00, h0, l0); split_bf16(v01, h1, l1);
                *reinterpret_cast<__nv_bfloat162*>(Chi + (size_t)m0 * HID + n0) = __nv_bfloat162(h0, h1);
                *reinterpret_cast<__nv_bfloat162*>(Clo + (size_t)m0 * HID + n0) = __nv_bfloat162(l0, l1);
                split_bf16(v10, h0, l0); split_bf16(v11, h1, l1);
                *reinterpret_cast<__nv_bfloat162*>(Chi + (size_t)(m0 + 8) * HID + n0) = __nv_bfloat162(h0, h1);
                *reinterpret_cast<__nv_bfloat162*>(Clo + (size_t)(m0 + 8) * HID + n0) = __nv_bfloat162(l0, l1);
            }
        }
    }
}

// ---------------- sequential scan: TWO chains per thread ---------------------
// Each thread owns hidden units (j, j+1) of one (batch, direction) — two
// independent recurrences interleaved in the instruction stream so MUFU
// latency of one chain is hidden by the other. Vector loads (bf162/float2)
// and vector stores (bf162/float2). 8192 threads, 32-thread blocks.
// Chain per step: v = a*h + c; e = ex2(v); h = 1 - 2*rcp(1+e).
// OM=0: write split bf16 planes. OM=1: write fp32 pairs into d_out.
#define SU 8
template <int OM>
__global__ void scan_tc(const __nv_bfloat16* __restrict__ xAhi, const __nv_bfloat16* __restrict__ xAlo,
                        const float* __restrict__ gA,
                        const __nv_bfloat16* __restrict__ xBhi, const __nv_bfloat16* __restrict__ xBlo,
                        const float* __restrict__ gB,
                        __nv_bfloat16* __restrict__ yAhi, __nv_bfloat16* __restrict__ yAlo,
                        __nv_bfloat16* __restrict__ yBhi, __nv_bfloat16* __restrict__ yBlo,
                        float* __restrict__ outF,
                        float* __restrict__ hA, float* __restrict__ hB)
{
    const int gid = blockIdx.x * 32 + threadIdx.x;   // 0..8191
    const int dir = gid >> 12;
    const int id  = gid & 4095;
    const int b = id >> 7;            // 0..31
    const int j = (id & 127) << 1;    // even j: chains j, j+1

    const __nv_bfloat16 *xh, *xl;
    const float* gp;
    __nv_bfloat16 *yh, *yl;
    float* hp;
    int t0, dt;
    if (dir == 0) { xh = xAhi; xl = xAlo; gp = gA; yh = yAhi; yl = yAlo;
                    hp = hA; t0 = 0;        dt =  1; }
    else          { xh = xBhi; xl = xBlo; gp = gB; yh = yBhi; yl = yBlo;
                    hp = hB; t0 = SEQL - 1; dt = -1; }

    const int base = b * SEQL * HID + j;
    const size_t obase = (size_t)b * SEQL * (2 * HID) + (size_t)dir * HID + j;

    float a0[2][SU], c0[2][SU], a1[2][SU], c1[2][SU];

    auto LOAD = [&](int s0, int bufi) {
#pragma unroll
        for (int u = 0; u < SU; u++) {
            const int t = t0 + dt * (s0 + u);
            const int idx = base + t * HID;
            const __nv_bfloat162 hh = *reinterpret_cast<const __nv_bfloat162*>(xh + idx);
            const __nv_bfloat162 ll = *reinterpret_cast<const __nv_bfloat162*>(xl + idx);
            const float2 gg = *reinterpret_cast<const float2*>(gp + idx);
            const float x0 = __bfloat162float(hh.x) + __bfloat162float(ll.x);
            const float x1 = __bfloat162float(hh.y) + __bfloat162float(ll.y);
            a0[bufi][u] = K2LOG2E * x0 * gg.x;
            c0[bufi][u] = K2LOG2E * x0 * x0 * (1.0f - gg.x);
            a1[bufi][u] = K2LOG2E * x1 * gg.y;
            c1[bufi][u] = K2LOG2E * x1 * x1 * (1.0f - gg.y);
        }
    };

    LOAD(0, 0);
    float h0 = 0.0f, h1 = 0.0f;
    int cur = 0;
    for (int s0 = 0; s0 < SEQL; s0 += SU) {
        const bool more = (s0 + SU) < SEQL;
        if (more) LOAD(s0 + SU, cur ^ 1);
#pragma unroll
        for (int u = 0; u < SU; u++) {
            const float v0 = fmaf(a0[cur][u], h0, c0[cur][u]);
            const float v1 = fmaf(a1[cur][u], h1, c1[cur][u]);
            const float e0 = fast_ex2(v0);
            const float e1 = fast_ex2(v1);
            h0 = fmaf(-2.0f, fast_rcp(e0 + 1.0f), 1.0f);
            h1 = fmaf(-2.0f, fast_rcp(e1 + 1.0f), 1.0f);
            const int tt = t0 + dt * (s0 + u);
            if (OM == 0) {
                __nv_bfloat16 hi0, lo0, hi1, lo1;
                split_bf16(h0, hi0, lo0); split_bf16(h1, hi1, lo1);
                *reinterpret_cast<__nv_bfloat162*>(yh + base + tt * HID) = __nv_bfloat162(hi0, hi1);
                *reinterpret_cast<__nv_bfloat162*>(yl + base + tt * HID) = __nv_bfloat162(lo0, lo1);
            } else {
                *reinterpret_cast<float2*>(outF + obase + (size_t)tt * (2 * HID))
                    = make_float2(h0, h1);
            }
        }
        cur ^= 1;
    }
    *reinterpret_cast<float2*>(hp + (b << 8) + j) = make_float2(h0, h1);
}

// ---------------- launch ----------------
extern "C" void kernel_launch(void* const* d_in, const int* in_sizes, int n_in,
                              void* d_out, int out_size)
{
    const float* x    = (const float*)d_in[0];  // [32,2048,512]
    const float* W_fc = (const float*)d_in[1];  // [256,512]
    const float* b_fc = (const float*)d_in[2];  // [256]
    // d_in[3] (W1), d_in[4] (b1): mathematically dead (blending1 == identity)
    const float* W2   = (const float*)d_in[5];  // [2,256,256]
    const float* b2   = (const float*)d_in[6];  // [2,256]
    float* out = (float*)d_out;

    __nv_bfloat16 *xhi, *xlo, *Wfc3, *W23, *Hhi, *Hlo, *Ylhi, *Yllo, *Yrhi, *Yrlo;
    float *G1, *Ga, *Gb, *hd;
    cudaGetSymbolAddress((void**)&xhi,  g_xhi);
    cudaGetSymbolAddress((void**)&xlo,  g_xlo);
    cudaGetSymbolAddress((void**)&Wfc3, g_Wfc3);
    cudaGetSymbolAddress((void**)&W23,  g_W23);
    cudaGetSymbolAddress((void**)&Hhi,  g_Hhi);
    cudaGetSymbolAddress((void**)&Hlo,  g_Hlo);
    cudaGetSymbolAddress((void**)&G1,   g_G1);
    cudaGetSymbolAddress((void**)&Ylhi, g_Ylhi);
    cudaGetSymbolAddress((void**)&Yllo, g_Yllo);
    cudaGetSymbolAddress((void**)&Yrhi, g_Yrhi);
    cudaGetSymbolAddress((void**)&Yrlo, g_Yrlo);
    cudaGetSymbolAddress((void**)&Ga,   g_Ga);
    cudaGetSymbolAddress((void**)&Gb,   g_Gb);
    cudaGetSymbolAddress((void**)&hd,   g_hdump);

    float* hout = (out_size >= XXN + HOUTN) ? (out + XXN) : hd;

    // 0) operand conversion (x -> hi/lo planes; W -> [Whi|Whi|Wlo])
    {
        int n4 = MTOT * INF / 4;
        convert_x_kernel<<<(n4 + 255) / 256, 256>>>(x, xhi, xlo, n4);
        int nw = HID * INF + 2 * HID * HID;
        convert_w_kernel<<<(nw + 255) / 256, 256>>>(W_fc, W2, Wfc3, W23);
    }

    const dim3 blk(256);
    const dim3 grd1(HID / 64, MTOT / 128, 1);   // bn fastest -> A reuse in L2
    const dim3 grd2(HID / 64, MTOT / 128, 2);

    // 1) input projection -> split bf16 H planes
    gemm_tc<0><<<grd1, blk>>>(xhi, xlo, nullptr, nullptr, Wfc3, b_fc,
                              nullptr, nullptr, Hhi, Hlo, INF);
    // 2) layer-1 gates (shared by both directions) -> fp32 G1
    gemm_tc<1><<<grd1, blk>>>(Hhi, Hlo, nullptr, nullptr, W23, b2,
                              G1, nullptr, nullptr, nullptr, HID);
    // 3) layer-1 scans (fwd+rev in one launch) -> split Y planes + h_out[0,1]
    scan_tc<0><<<256, 32>>>(Hhi, Hlo, G1, Hhi, Hlo, G1,
                            Ylhi, Yllo, Yrhi, Yrlo,
                            nullptr, hout, hout + BSZ * HID);
    // 4) layer-2 gates, both directions fused via gridDim.z -> Ga, Gb
    gemm_tc<1><<<grd2, blk>>>(Ylhi, Yllo, Yrhi, Yrlo,
                              W23 + (size_t)HID * 3 * HID, b2 + HID,
                              Ga, Gb, nullptr, nullptr, HID);
    // 5) layer-2 scans write straight into d_out + h_out[2,3]
    scan_tc<1><<<256, 32>>>(Ylhi, Yllo, Ga, Yrhi, Yrlo, Gb,
                            nullptr, nullptr, nullptr, nullptr,
                            out, hout + 2 * BSZ * HID, hout + 3 * BSZ * HID);
}

// round 10
// speedup vs baseline: 1.3477x; 1.2042x over previous
#include <cuda_runtime.h>
#include <cuda_bf16.h>
#include <math.h>
#include <stdint.h>

#define BSZ 32
#define SEQL 2048
#define INF 512
#define HID 256
#define MTOT (BSZ * SEQL)           // 65536 rows
#define XXN (BSZ * SEQL * 2 * HID)  // 33554432
#define HOUTN (4 * BSZ * HID)       // 32768

// ---------------- scratch (static device globals; no allocation) -------------
__device__ __nv_bfloat16 g_xhi [MTOT * INF];
__device__ __nv_bfloat16 g_xlo [MTOT * INF];
__device__ __nv_bfloat16 g_Wfc3[HID * 3 * INF];       // [Whi|Whi|Wlo] along k'
__device__ __nv_bfloat16 g_W23 [2 * HID * 3 * HID];
__device__ __nv_bfloat16 g_Hhi [MTOT * HID];
__device__ __nv_bfloat16 g_Hlo [MTOT * HID];
__device__ float         g_G1  [MTOT * HID];
__device__ __nv_bfloat16 g_Ylhi[MTOT * HID];
__device__ __nv_bfloat16 g_Yllo[MTOT * HID];
__device__ __nv_bfloat16 g_Yrhi[MTOT * HID];
__device__ __nv_bfloat16 g_Yrlo[MTOT * HID];
__device__ float         g_Ga  [MTOT * HID];
__device__ float         g_Gb  [MTOT * HID];
__device__ float         g_hdump[4 * BSZ * HID];

#define K2LOG2E 2.8853900817779268f   // 2*log2(e)

// ---------------- fast math ----------------
__device__ __forceinline__ float fast_ex2(float x) {
    float y; asm("ex2.approx.f32 %0, %1;" : "=f"(y) : "f"(x)); return y;
}
__device__ __forceinline__ float fast_rcp(float x) {
    float y; asm("rcp.approx.f32 %0, %1;" : "=f"(y) : "f"(x)); return y;
}
__device__ __forceinline__ float fast_sigmoid(float z) {
    return fast_rcp(1.0f + fast_ex2(-1.4426950408889634f * z));
}
__device__ __forceinline__ void split_bf16(float v, __nv_bfloat16& hi, __nv_bfloat16& lo) {
    hi = __float2bfloat16(v);
    lo = __float2bfloat16(v - __bfloat162float(hi));
}

// ---------------- PTX helpers ----------------
__device__ __forceinline__ void ldsm4(uint32_t (&r)[4], uint32_t saddr) {
    asm volatile("ldmatrix.sync.aligned.m8n8.x4.shared.b16 {%0,%1,%2,%3}, [%4];"
                 : "=r"(r[0]), "=r"(r[1]), "=r"(r[2]), "=r"(r[3]) : "r"(saddr));
}
__device__ __forceinline__ void mma16816(float (&d)[4], const uint32_t (&a)[4],
                                         uint32_t b0, uint32_t b1) {
    asm volatile("mma.sync.aligned.m16n8k16.row.col.f32.bf16.bf16.f32 "
                 "{%0,%1,%2,%3}, {%4,%5,%6,%7}, {%8,%9}, {%0,%1,%2,%3};"
                 : "+f"(d[0]), "+f"(d[1]), "+f"(d[2]), "+f"(d[3])
                 : "r"(a[0]), "r"(a[1]), "r"(a[2]), "r"(a[3]), "r"(b0), "r"(b1));
}
__device__ __forceinline__ void cpa16(uint32_t s, const void* g) {
    asm volatile("cp.async.cg.shared.global [%0], [%1], 16;" :: "r"(s), "l"(g));
}
__device__ __forceinline__ void cpa_commit() { asm volatile("cp.async.commit_group;"); }

// ---------------- conversion kernels ----------------
__global__ void convert_x_kernel(const float* __restrict__ x,
                                 __nv_bfloat16* __restrict__ xhi,
                                 __nv_bfloat16* __restrict__ xlo, int n4)
{
    int i = blockIdx.x * blockDim.x + threadIdx.x;
    if (i >= n4) return;
    float4 v = reinterpret_cast<const float4*>(x)[i];
    __nv_bfloat16 h0, l0, h1, l1, h2, l2, h3, l3;
    split_bf16(v.x, h0, l0); split_bf16(v.y, h1, l1);
    split_bf16(v.z, h2, l2); split_bf16(v.w, h3, l3);
    reinterpret_cast<__nv_bfloat162*>(xhi)[2 * i]     = __nv_bfloat162(h0, h1);
    reinterpret_cast<__nv_bfloat162*>(xhi)[2 * i + 1] = __nv_bfloat162(h2, h3);
    reinterpret_cast<__nv_bfloat162*>(xlo)[2 * i]     = __nv_bfloat162(l0, l1);
    reinterpret_cast<__nv_bfloat162*>(xlo)[2 * i + 1] = __nv_bfloat162(l2, l3);
}

// Build W' = [Whi | Whi | Wlo] (k' = 3K) for W_fc and both W2 layers.
__global__ void convert_w_kernel(const float* __restrict__ Wfc,
                                 const float* __restrict__ W2,
                                 __nv_bfloat16* __restrict__ Wfc3,
                                 __nv_bfloat16* __restrict__ W23)
{
    int i = blockIdx.x * blockDim.x + threadIdx.x;
    const int t1 = HID * INF;
    const int t2 = 2 * HID * HID;
    if (i < t1) {
        int n = i / INF, k = i % INF;
        __nv_bfloat16 hi, lo; split_bf16(Wfc[i], hi, lo);
        __nv_bfloat16* base = Wfc3 + (size_t)n * (3 * INF);
        base[k] = hi; base[INF + k] = hi; base[2 * INF + k] = lo;
    } else if (i < t1 + t2) {
        int j = i - t1;
        int l = j / (HID * HID); int r = j % (HID * HID);
        int n = r / HID, k = r % HID;
        __nv_bfloat16 hi, lo; split_bf16(W2[j], hi, lo);
        __nv_bfloat16* base = W23 + (size_t)l * HID * (3 * HID) + (size_t)n * (3 * HID);
        base[k] = hi; base[HID + k] = hi; base[2 * HID + k] = lo;
    }
}

// ---------------- tensor-core GEMM (unchanged from R9 — proven) --------------
// Block tile 128x64, 8 warps (32x32 each), k-chunk 32, 3-stage cp.async
// circular pipeline, ONE __syncthreads per chunk, ldsm/mma fragment
// double-buffering. Grid: (N/64, M/128, nz) — bn fastest for A reuse in L2.
// OUT=0: C = A@W'^T + bias -> split bf16 planes Chi/Clo.
// OUT=1: g = sigmoid(acc + bias) -> fp32 G plane.
#define A_STRIDE 40
#define A_TILE (128 * A_STRIDE)
#define W_TILE (64 * A_STRIDE)
#define NSTG 3

template <int OUT>
__global__ __launch_bounds__(256, 2)
void gemm_tc(const __nv_bfloat16* __restrict__ Ahi_, const __nv_bfloat16* __restrict__ Alo_,
             const __nv_bfloat16* __restrict__ Ahi2, const __nv_bfloat16* __restrict__ Alo2,
             const __nv_bfloat16* __restrict__ W3, const float* __restrict__ bias,
             float* __restrict__ Ga, float* __restrict__ Gb,
             __nv_bfloat16* __restrict__ Chi, __nv_bfloat16* __restrict__ Clo, int K)
{
    __shared__ __nv_bfloat16 As[NSTG][A_TILE];
    __shared__ __nv_bfloat16 Ws[NSTG][W_TILE];

    const __nv_bfloat16* Ahi = (blockIdx.z == 0) ? Ahi_ : Ahi2;
    const __nv_bfloat16* Alo = (blockIdx.z == 0) ? Alo_ : Alo2;
    float* G = (blockIdx.z == 0) ? Ga : Gb;

    const int tid  = threadIdx.x;
    const int bm   = blockIdx.y * 128;
    const int bn   = blockIdx.x * 64;
    const int warp = tid >> 5;
    const int lane = tid & 31;
    const int K3   = 3 * K;
    const int n1   = K >> 5;
    const int nc   = 3 * n1;

    const uint32_t sA = (uint32_t)__cvta_generic_to_shared(&As[0][0]);
    const uint32_t sW = (uint32_t)__cvta_generic_to_shared(&Ws[0][0]);

    const int ar0 = tid >> 2, ar1 = (tid + 256) >> 2;
    const int ac  = (tid & 3) * 8;
    const int wr  = tid >> 2;
    const uint32_t sAoff0 = (uint32_t)(ar0 * A_STRIDE + ac) * 2;
    const uint32_t sAoff1 = (uint32_t)(ar1 * A_STRIDE + ac) * 2;
    const uint32_t sWoff  = (uint32_t)(wr  * A_STRIDE + ac) * 2;
    const __nv_bfloat16* Wg = W3 + (size_t)(bn + wr) * K3 + ac;

    float acc[2][4][4];
#pragma unroll
    for (int a = 0; a < 2; a++)
#pragma unroll
        for (int b = 0; b < 4; b++)
#pragma unroll
            for (int c = 0; c < 4; c++) acc[a][b][c] = 0.0f;

    auto prefetch = [&](int c, int buf) {
        const __nv_bfloat16* Aseg; int kk;
        if (c < n1)           { Aseg = Ahi; kk = c; }
        else if (c < 2 * n1)  { Aseg = Alo; kk = c - n1; }
        else                  { Aseg = Ahi; kk = c - 2 * n1; }
        const __nv_bfloat16* Abase = Aseg + (size_t)bm * K + kk * 32 + ac;
        cpa16(sA + buf * (A_TILE * 2) + sAoff0, Abase + (size_t)ar0 * K);
        cpa16(sA + buf * (A_TILE * 2) + sAoff1, Abase + (size_t)ar1 * K);
        cpa16(sW + buf * (W_TILE * 2) + sWoff,  Wg + c * 32);
    };

    const int wm = warp & 3;
    const int wn = warp >> 2;
    const int aRow = wm * 32 + (lane & 15);
    const int aColB = (lane >> 4) * 8;
    const int bRow = wn * 32 + (lane & 7) + ((lane >> 4) & 1) * 8;
    const int bColB = ((lane >> 3) & 1) * 8;

    uint32_t afr[2][2][4], bfr[2][2][4];

    auto load_frags = [&](int buf, int ks, int slot) {
        const uint32_t aBase = sA + buf * (A_TILE * 2);
        const uint32_t wBase = sW + buf * (W_TILE * 2);
#pragma unroll
        for (int mi = 0; mi < 2; mi++)
            ldsm4(afr[slot][mi], aBase + (uint32_t)((aRow + mi * 16) * A_STRIDE
                                                    + ks * 16 + aColB) * 2);
#pragma unroll
        for (int bi = 0; bi < 2; bi++)
            ldsm4(bfr[slot][bi], wBase + (uint32_t)((bRow + bi * 16) * A_STRIDE
                                                    + ks * 16 + bColB) * 2);
    };
    auto do_mma = [&](int slot) {
#pragma unroll
        for (int mi = 0; mi < 2; mi++) {
            mma16816(acc[mi][0], afr[slot][mi], bfr[slot][0][0], bfr[slot][0][1]);
            mma16816(acc[mi][1], afr[slot][mi], bfr[slot][0][2], bfr[slot][0][3]);
            mma16816(acc[mi][2], afr[slot][mi], bfr[slot][1][0], bfr[slot][1][1]);
            mma16816(acc[mi][3], afr[slot][mi], bfr[slot][1][2], bfr[slot][1][3]);
        }
    };

    prefetch(0, 0); cpa_commit();
    prefetch(1, 1); cpa_commit();
    asm volatile("cp.async.wait_group 1;");
    __syncthreads();
    load_frags(0, 0, 0);

    int buf = 0;
    for (int c = 0; c < nc; c++) {
        load_frags(buf, 1, 1);
        do_mma(0);
        if (c + 2 < nc) {
            int pf = buf + 2; if (pf >= NSTG) pf -= NSTG;
            prefetch(c + 2, pf);
            cpa_commit();
            asm volatile("cp.async.wait_group 1;");
        } else {
            asm volatile("cp.async.wait_group 0;");
        }
        __syncthreads();
        const int nbuf = (buf + 1 == NSTG) ? 0 : buf + 1;
        if (c + 1 < nc) load_frags(nbuf, 0, 0);
        do_mma(1);
        buf = nbuf;
    }

    // epilogue
#pragma unroll
    for (int mi = 0; mi < 2; mi++) {
#pragma unroll
        for (int ni = 0; ni < 4; ni++) {
            const int m0 = bm + wm * 32 + mi * 16 + (lane >> 2);
            const int n0 = bn + wn * 32 + ni * 8 + (lane & 3) * 2;
            const float b0 = bias[n0], b1 = bias[n0 + 1];
            float v00 = acc[mi][ni][0] + b0, v01 = acc[mi][ni][1] + b1;
            float v10 = acc[mi][ni][2] + b0, v11 = acc[mi][ni][3] + b1;
            if (OUT == 1) {
                v00 = fast_sigmoid(v00); v01 = fast_sigmoid(v01);
                v10 = fast_sigmoid(v10); v11 = fast_sigmoid(v11);
                *reinterpret_cast<float2*>(G + (size_t)m0 * HID + n0)       = make_float2(v00, v01);
                *reinterpret_cast<float2*>(G + (size_t)(m0 + 8) * HID + n0) = make_float2(v10, v11);
            } else {
                __nv_bfloat16 h0, l0, h1, l1;
                split_bf16(v00, h0, l0); split_bf16(v01, h1, l1);
                *reinterpret_cast<__nv_bfloat162*>(Chi + (size_t)m0 * HID + n0) = __nv_bfloat162(h0, h1);
                *reinterpret_cast<__nv_bfloat162*>(Clo + (size_t)m0 * HID + n0) = __nv_bfloat162(l0, l1);
                split_bf16(v10, h0, l0); split_bf16(v11, h1, l1);
                *reinterpret_cast<__nv_bfloat162*>(Chi + (size_t)(m0 + 8) * HID + n0) = __nv_bfloat162(h0, h1);
                *reinterpret_cast<__nv_bfloat162*>(Clo + (size_t)(m0 + 8) * HID + n0) = __nv_bfloat162(l0, l1);
            }
        }
    }
}

// ---------------- sequential scan: 2 chains/thread, STATIC ping-pong ---------
// The prefetch double-buffer uses statically named register arrays with
// compile-time indices only (macros over distinct arrays; outer loop unrolled
// A/B) — no runtime-indexed first dimension, so no local-memory demotion.
// Chain per step: v = a*h + c; e = ex2(v); h = 1 - 2*rcp(1+e). Two independent
// chains interleave to cover MUFU latency.
#define SU 8

#define SCAN_LOAD(s0, A0, C0, A1, C1)                                          \
    do {                                                                        \
        _Pragma("unroll")                                                       \
        for (int u = 0; u < SU; u++) {                                          \
            const int t = t0 + dt * ((s0) + u);                                 \
            const int idx = base + t * HID;                                     \
            const __nv_bfloat162 hh = *reinterpret_cast<const __nv_bfloat162*>(xh + idx); \
            const __nv_bfloat162 ll = *reinterpret_cast<const __nv_bfloat162*>(xl + idx); \
            const float2 gg = *reinterpret_cast<const float2*>(gp + idx);       \
            const float x0 = __bfloat162float(hh.x) + __bfloat162float(ll.x);   \
            const float x1 = __bfloat162float(hh.y) + __bfloat162float(ll.y);   \
            A0[u] = K2LOG2E * x0 * gg.x;                                        \
            C0[u] = K2LOG2E * x0 * x0 * (1.0f - gg.x);                          \
            A1[u] = K2LOG2E * x1 * gg.y;                                        \
            C1[u] = K2LOG2E * x1 * x1 * (1.0f - gg.y);                          \
        }                                                                       \
    } while (0)

#define SCAN_STEP(s0, A0, C0, A1, C1)                                           \
    do {                                                                        \
        _Pragma("unroll")                                                       \
        for (int u = 0; u < SU; u++) {                                          \
            const float v0 = fmaf(A0[u], h0, C0[u]);                            \
            const float v1 = fmaf(A1[u], h1, C1[u]);                            \
            const float e0 = fast_ex2(v0);                                      \
            const float e1 = fast_ex2(v1);                                      \
            h0 = fmaf(-2.0f, fast_rcp(e0 + 1.0f), 1.0f);                        \
            h1 = fmaf(-2.0f, fast_rcp(e1 + 1.0f), 1.0f);                        \
            const int tt = t0 + dt * ((s0) + u);                                \
            if (OM == 0) {                                                      \
                __nv_bfloat16 hi0, lo0, hi1, lo1;                               \
                split_bf16(h0, hi0, lo0); split_bf16(h1, hi1, lo1);             \
                *reinterpret_cast<__nv_bfloat162*>(yh + base + tt * HID)        \
                    = __nv_bfloat162(hi0, hi1);                                 \
                *reinterpret_cast<__nv_bfloat162*>(yl + base + tt * HID)        \
                    = __nv_bfloat162(lo0, lo1);                                 \
            } else {                                                            \
                *reinterpret_cast<float2*>(outF + obase + (size_t)tt * (2 * HID)) \
                    = make_float2(h0, h1);                                      \
            }                                                                   \
        }                                                                       \
    } while (0)

template <int OM>
__global__ __launch_bounds__(64)
void scan_tc(const __nv_bfloat16* __restrict__ xAhi, const __nv_bfloat16* __restrict__ xAlo,
             const float* __restrict__ gA,
             const __nv_bfloat16* __restrict__ xBhi, const __nv_bfloat16* __restrict__ xBlo,
             const float* __restrict__ gB,
             __nv_bfloat16* __restrict__ yAhi, __nv_bfloat16* __restrict__ yAlo,
             __nv_bfloat16* __restrict__ yBhi, __nv_bfloat16* __restrict__ yBlo,
             float* __restrict__ outF,
             float* __restrict__ hA, float* __restrict__ hB)
{
    const int gid = blockIdx.x * 64 + threadIdx.x;   // 0..8191
    const int dir = gid >> 12;
    const int id  = gid & 4095;
    const int b = id >> 7;            // 0..31
    const int j = (id & 127) << 1;    // even j: chains j, j+1

    const __nv_bfloat16 *xh, *xl;
    const float* gp;
    __nv_bfloat16 *yh, *yl;
    float* hp;
    int t0, dt;
    if (dir == 0) { xh = xAhi; xl = xAlo; gp = gA; yh = yAhi; yl = yAlo;
                    hp = hA; t0 = 0;        dt =  1; }
    else          { xh = xBhi; xl = xBlo; gp = gB; yh = yBhi; yl = yBlo;
                    hp = hB; t0 = SEQL - 1; dt = -1; }

    const int base = b * SEQL * HID + j;
    const size_t obase = (size_t)b * SEQL * (2 * HID) + (size_t)dir * HID + j;

    // statically named ping-pong buffers (register-resident by construction)
    float a0A[SU], c0A[SU], a1A[SU], c1A[SU];
    float a0B[SU], c0B[SU], a1B[SU], c1B[SU];

    float h0 = 0.0f, h1 = 0.0f;

    SCAN_LOAD(0, a0A, c0A, a1A, c1A);
    for (int s0 = 0; s0 < SEQL; s0 += 2 * SU) {
        SCAN_LOAD(s0 + SU, a0B, c0B, a1B, c1B);      // prefetch batch B
        SCAN_STEP(s0, a0A, c0A, a1A, c1A);           // consume batch A
        if (s0 + 2 * SU < SEQL)
            SCAN_LOAD(s0 + 2 * SU, a0A, c0A, a1A, c1A);  // prefetch batch A'
        SCAN_STEP(s0 + SU, a0B, c0B, a1B, c1B);      // consume batch B
    }
    *reinterpret_cast<float2*>(hp + (b << 8) + j) = make_float2(h0, h1);
}

// ---------------- launch ----------------
extern "C" void kernel_launch(void* const* d_in, const int* in_sizes, int n_in,
                              void* d_out, int out_size)
{
    const float* x    = (const float*)d_in[0];  // [32,2048,512]
    const float* W_fc = (const float*)d_in[1];  // [256,512]
    const float* b_fc = (const float*)d_in[2];  // [256]
    // d_in[3] (W1), d_in[4] (b1): mathematically dead (blending1 == identity)
    const float* W2   = (const float*)d_in[5];  // [2,256,256]
    const float* b2   = (const float*)d_in[6];  // [2,256]
    float* out = (float*)d_out;

    __nv_bfloat16 *xhi, *xlo, *Wfc3, *W23, *Hhi, *Hlo, *Ylhi, *Yllo, *Yrhi, *Yrlo;
    float *G1, *Ga, *Gb, *hd;
    cudaGetSymbolAddress((void**)&xhi,  g_xhi);
    cudaGetSymbolAddress((void**)&xlo,  g_xlo);
    cudaGetSymbolAddress((void**)&Wfc3, g_Wfc3);
    cudaGetSymbolAddress((void**)&W23,  g_W23);
    cudaGetSymbolAddress((void**)&Hhi,  g_Hhi);
    cudaGetSymbolAddress((void**)&Hlo,  g_Hlo);
    cudaGetSymbolAddress((void**)&G1,   g_G1);
    cudaGetSymbolAddress((void**)&Ylhi, g_Ylhi);
    cudaGetSymbolAddress((void**)&Yllo, g_Yllo);
    cudaGetSymbolAddress((void**)&Yrhi, g_Yrhi);
    cudaGetSymbolAddress((void**)&Yrlo, g_Yrlo);
    cudaGetSymbolAddress((void**)&Ga,   g_Ga);
    cudaGetSymbolAddress((void**)&Gb,   g_Gb);
    cudaGetSymbolAddress((void**)&hd,   g_hdump);

    float* hout = (out_size >= XXN + HOUTN) ? (out + XXN) : hd;

    // 0) operand conversion (x -> hi/lo planes; W -> [Whi|Whi|Wlo])
    {
        int n4 = MTOT * INF / 4;
        convert_x_kernel<<<(n4 + 255) / 256, 256>>>(x, xhi, xlo, n4);
        int nw = HID * INF + 2 * HID * HID;
        convert_w_kernel<<<(nw + 255) / 256, 256>>>(W_fc, W2, Wfc3, W23);
    }

    const dim3 blk(256);
    const dim3 grd1(HID / 64, MTOT / 128, 1);   // bn fastest -> A reuse in L2
    const dim3 grd2(HID / 64, MTOT / 128, 2);

    // 1) input projection -> split bf16 H planes
    gemm_tc<0><<<grd1, blk>>>(xhi, xlo, nullptr, nullptr, Wfc3, b_fc,
                              nullptr, nullptr, Hhi, Hlo, INF);
    // 2) layer-1 gates (shared by both directions) -> fp32 G1
    gemm_tc<1><<<grd1, blk>>>(Hhi, Hlo, nullptr, nullptr, W23, b2,
                              G1, nullptr, nullptr, nullptr, HID);
    // 3) layer-1 scans (fwd+rev in one launch) -> split Y planes + h_out[0,1]
    scan_tc<0><<<128, 64>>>(Hhi, Hlo, G1, Hhi, Hlo, G1,
                            Ylhi, Yllo, Yrhi, Yrlo,
                            nullptr, hout, hout + BSZ * HID);
    // 4) layer-2 gates, both directions fused via gridDim.z -> Ga, Gb
    gemm_tc<1><<<grd2, blk>>>(Ylhi, Yllo, Yrhi, Yrlo,
                              W23 + (size_t)HID * 3 * HID, b2 + HID,
                              Ga, Gb, nullptr, nullptr, HID);
    // 5) layer-2 scans write straight into d_out + h_out[2,3]
    scan_tc<1><<<128, 64>>>(Ylhi, Yllo, Ga, Yrhi, Yrlo, Gb,
                            nullptr, nullptr, nullptr, nullptr,
                            out, hout + 2 * BSZ * HID, hout + 3 * BSZ * HID);
}

// round 11
// speedup vs baseline: 1.4930x; 1.1078x over previous
#include <cuda_runtime.h>
#include <cuda_bf16.h>
#include <math.h>
#include <stdint.h>

#define BSZ 32
#define SEQL 2048
#define INF 512
#define HID 256
#define MTOT (BSZ * SEQL)           // 65536 rows
#define XXN (BSZ * SEQL * 2 * HID)  // 33554432
#define HOUTN (4 * BSZ * HID)       // 32768

// ---------------- scratch (static device globals; no allocation) -------------
__device__ __nv_bfloat16 g_xhi [MTOT * INF];
__device__ __nv_bfloat16 g_xlo [MTOT * INF];
__device__ __nv_bfloat16 g_Wfc3[HID * 3 * INF];       // [Whi|Whi|Wlo] along k'
__device__ __nv_bfloat16 g_W23 [2 * HID * 3 * HID];
__device__ __nv_bfloat16 g_Hhi [MTOT * HID];
__device__ __nv_bfloat16 g_Hlo [MTOT * HID];
__device__ float         g_G1  [MTOT * HID];
__device__ __nv_bfloat16 g_Ylhi[MTOT * HID];
__device__ __nv_bfloat16 g_Yllo[MTOT * HID];
__device__ __nv_bfloat16 g_Yrhi[MTOT * HID];
__device__ __nv_bfloat16 g_Yrlo[MTOT * HID];
__device__ float         g_Ga  [MTOT * HID];
__device__ float         g_Gb  [MTOT * HID];
__device__ float         g_hdump[4 * BSZ * HID];

#define K2LOG2E 2.8853900817779268f   // 2*log2(e)

// ---------------- fast math ----------------
__device__ __forceinline__ float fast_ex2(float x) {
    float y; asm("ex2.approx.f32 %0, %1;" : "=f"(y) : "f"(x)); return y;
}
__device__ __forceinline__ float fast_rcp(float x) {
    float y; asm("rcp.approx.f32 %0, %1;" : "=f"(y) : "f"(x)); return y;
}
__device__ __forceinline__ float fast_sigmoid(float z) {
    return fast_rcp(1.0f + fast_ex2(-1.4426950408889634f * z));
}
__device__ __forceinline__ void split_bf16(float v, __nv_bfloat16& hi, __nv_bfloat16& lo) {
    hi = __float2bfloat16(v);
    lo = __float2bfloat16(v - __bfloat162float(hi));
}

// ---------------- PTX helpers ----------------
__device__ __forceinline__ void ldsm4(uint32_t (&r)[4], uint32_t saddr) {
    asm volatile("ldmatrix.sync.aligned.m8n8.x4.shared.b16 {%0,%1,%2,%3}, [%4];"
                 : "=r"(r[0]), "=r"(r[1]), "=r"(r[2]), "=r"(r[3]) : "r"(saddr));
}
__device__ __forceinline__ void mma16816(float (&d)[4], const uint32_t (&a)[4],
                                         uint32_t b0, uint32_t b1) {
    asm volatile("mma.sync.aligned.m16n8k16.row.col.f32.bf16.bf16.f32 "
                 "{%0,%1,%2,%3}, {%4,%5,%6,%7}, {%8,%9}, {%0,%1,%2,%3};"
                 : "+f"(d[0]), "+f"(d[1]), "+f"(d[2]), "+f"(d[3])
                 : "r"(a[0]), "r"(a[1]), "r"(a[2]), "r"(a[3]), "r"(b0), "r"(b1));
}
__device__ __forceinline__ void cpa16(uint32_t s, const void* g) {
    asm volatile("cp.async.cg.shared.global [%0], [%1], 16;" :: "r"(s), "l"(g));
}
__device__ __forceinline__ void cpa_commit() { asm volatile("cp.async.commit_group;"); }

// ---------------- conversion kernels ----------------
__global__ void convert_x_kernel(const float* __restrict__ x,
                                 __nv_bfloat16* __restrict__ xhi,
                                 __nv_bfloat16* __restrict__ xlo, int n4)
{
    int i = blockIdx.x * blockDim.x + threadIdx.x;
    if (i >= n4) return;
    float4 v = reinterpret_cast<const float4*>(x)[i];
    __nv_bfloat16 h0, l0, h1, l1, h2, l2, h3, l3;
    split_bf16(v.x, h0, l0); split_bf16(v.y, h1, l1);
    split_bf16(v.z, h2, l2); split_bf16(v.w, h3, l3);
    reinterpret_cast<__nv_bfloat162*>(xhi)[2 * i]     = __nv_bfloat162(h0, h1);
    reinterpret_cast<__nv_bfloat162*>(xhi)[2 * i + 1] = __nv_bfloat162(h2, h3);
    reinterpret_cast<__nv_bfloat162*>(xlo)[2 * i]     = __nv_bfloat162(l0, l1);
    reinterpret_cast<__nv_bfloat162*>(xlo)[2 * i + 1] = __nv_bfloat162(l2, l3);
}

// Build W' = [Whi | Whi | Wlo] (k' = 3K) for W_fc and both W2 layers.
__global__ void convert_w_kernel(const float* __restrict__ Wfc,
                                 const float* __restrict__ W2,
                                 __nv_bfloat16* __restrict__ Wfc3,
                                 __nv_bfloat16* __restrict__ W23)
{
    int i = blockIdx.x * blockDim.x + threadIdx.x;
    const int t1 = HID * INF;
    const int t2 = 2 * HID * HID;
    if (i < t1) {
        int n = i / INF, k = i % INF;
        __nv_bfloat16 hi, lo; split_bf16(Wfc[i], hi, lo);
        __nv_bfloat16* base = Wfc3 + (size_t)n * (3 * INF);
        base[k] = hi; base[INF + k] = hi; base[2 * INF + k] = lo;
    } else if (i < t1 + t2) {
        int j = i - t1;
        int l = j / (HID * HID); int r = j % (HID * HID);
        int n = r / HID, k = r % HID;
        __nv_bfloat16 hi, lo; split_bf16(W2[j], hi, lo);
        __nv_bfloat16* base = W23 + (size_t)l * HID * (3 * HID) + (size_t)n * (3 * HID);
        base[k] = hi; base[HID + k] = hi; base[2 * HID + k] = lo;
    }
}

// ---------------- tensor-core GEMM (unchanged from R10 — proven) -------------
// Block tile 128x64, 8 warps (32x32 each), k-chunk 32, 3-stage cp.async
// circular pipeline, ONE __syncthreads per chunk, ldsm/mma fragment
// double-buffering. Grid: (N/64, M/128, nz) — bn fastest for A reuse in L2.
// OUT=0: C = A@W'^T + bias -> split bf16 planes Chi/Clo.
// OUT=1: g = sigmoid(acc + bias) -> fp32 G plane.
#define A_STRIDE 40
#define A_TILE (128 * A_STRIDE)
#define W_TILE (64 * A_STRIDE)
#define NSTG 3

template <int OUT>
__global__ __launch_bounds__(256, 2)
void gemm_tc(const __nv_bfloat16* __restrict__ Ahi_, const __nv_bfloat16* __restrict__ Alo_,
             const __nv_bfloat16* __restrict__ Ahi2, const __nv_bfloat16* __restrict__ Alo2,
             const __nv_bfloat16* __restrict__ W3, const float* __restrict__ bias,
             float* __restrict__ Ga, float* __restrict__ Gb,
             __nv_bfloat16* __restrict__ Chi, __nv_bfloat16* __restrict__ Clo, int K)
{
    __shared__ __nv_bfloat16 As[NSTG][A_TILE];
    __shared__ __nv_bfloat16 Ws[NSTG][W_TILE];

    const __nv_bfloat16* Ahi = (blockIdx.z == 0) ? Ahi_ : Ahi2;
    const __nv_bfloat16* Alo = (blockIdx.z == 0) ? Alo_ : Alo2;
    float* G = (blockIdx.z == 0) ? Ga : Gb;

    const int tid  = threadIdx.x;
    const int bm   = blockIdx.y * 128;
    const int bn   = blockIdx.x * 64;
    const int warp = tid >> 5;
    const int lane = tid & 31;
    const int K3   = 3 * K;
    const int n1   = K >> 5;
    const int nc   = 3 * n1;

    const uint32_t sA = (uint32_t)__cvta_generic_to_shared(&As[0][0]);
    const uint32_t sW = (uint32_t)__cvta_generic_to_shared(&Ws[0][0]);

    const int ar0 = tid >> 2, ar1 = (tid + 256) >> 2;
    const int ac  = (tid & 3) * 8;
    const int wr  = tid >> 2;
    const uint32_t sAoff0 = (uint32_t)(ar0 * A_STRIDE + ac) * 2;
    const uint32_t sAoff1 = (uint32_t)(ar1 * A_STRIDE + ac) * 2;
    const uint32_t sWoff  = (uint32_t)(wr  * A_STRIDE + ac) * 2;
    const __nv_bfloat16* Wg = W3 + (size_t)(bn + wr) * K3 + ac;

    float acc[2][4][4];
#pragma unroll
    for (int a = 0; a < 2; a++)
#pragma unroll
        for (int b = 0; b < 4; b++)
#pragma unroll
            for (int c = 0; c < 4; c++) acc[a][b][c] = 0.0f;

    auto prefetch = [&](int c, int buf) {
        const __nv_bfloat16* Aseg; int kk;
        if (c < n1)           { Aseg = Ahi; kk = c; }
        else if (c < 2 * n1)  { Aseg = Alo; kk = c - n1; }
        else                  { Aseg = Ahi; kk = c - 2 * n1; }
        const __nv_bfloat16* Abase = Aseg + (size_t)bm * K + kk * 32 + ac;
        cpa16(sA + buf * (A_TILE * 2) + sAoff0, Abase + (size_t)ar0 * K);
        cpa16(sA + buf * (A_TILE * 2) + sAoff1, Abase + (size_t)ar1 * K);
        cpa16(sW + buf * (W_TILE * 2) + sWoff,  Wg + c * 32);
    };

    const int wm = warp & 3;
    const int wn = warp >> 2;
    const int aRow = wm * 32 + (lane & 15);
    const int aColB = (lane >> 4) * 8;
    const int bRow = wn * 32 + (lane & 7) + ((lane >> 4) & 1) * 8;
    const int bColB = ((lane >> 3) & 1) * 8;

    uint32_t afr[2][2][4], bfr[2][2][4];

    auto load_frags = [&](int buf, int ks, int slot) {
        const uint32_t aBase = sA + buf * (A_TILE * 2);
        const uint32_t wBase = sW + buf * (W_TILE * 2);
#pragma unroll
        for (int mi = 0; mi < 2; mi++)
            ldsm4(afr[slot][mi], aBase + (uint32_t)((aRow + mi * 16) * A_STRIDE
                                                    + ks * 16 + aColB) * 2);
#pragma unroll
        for (int bi = 0; bi < 2; bi++)
            ldsm4(bfr[slot][bi], wBase + (uint32_t)((bRow + bi * 16) * A_STRIDE
                                                    + ks * 16 + bColB) * 2);
    };
    auto do_mma = [&](int slot) {
#pragma unroll
        for (int mi = 0; mi < 2; mi++) {
            mma16816(acc[mi][0], afr[slot][mi], bfr[slot][0][0], bfr[slot][0][1]);
            mma16816(acc[mi][1], afr[slot][mi], bfr[slot][0][2], bfr[slot][0][3]);
            mma16816(acc[mi][2], afr[slot][mi], bfr[slot][1][0], bfr[slot][1][1]);
            mma16816(acc[mi][3], afr[slot][mi], bfr[slot][1][2], bfr[slot][1][3]);
        }
    };

    prefetch(0, 0); cpa_commit();
    prefetch(1, 1); cpa_commit();
    asm volatile("cp.async.wait_group 1;");
    __syncthreads();
    load_frags(0, 0, 0);

    int buf = 0;
    for (int c = 0; c < nc; c++) {
        load_frags(buf, 1, 1);
        do_mma(0);
        if (c + 2 < nc) {
            int pf = buf + 2; if (pf >= NSTG) pf -= NSTG;
            prefetch(c + 2, pf);
            cpa_commit();
            asm volatile("cp.async.wait_group 1;");
        } else {
            asm volatile("cp.async.wait_group 0;");
        }
        __syncthreads();
        const int nbuf = (buf + 1 == NSTG) ? 0 : buf + 1;
        if (c + 1 < nc) load_frags(nbuf, 0, 0);
        do_mma(1);
        buf = nbuf;
    }

    // epilogue
#pragma unroll
    for (int mi = 0; mi < 2; mi++) {
#pragma unroll
        for (int ni = 0; ni < 4; ni++) {
            const int m0 = bm + wm * 32 + mi * 16 + (lane >> 2);
            const int n0 = bn + wn * 32 + ni * 8 + (lane & 3) * 2;
            const float b0 = bias[n0], b1 = bias[n0 + 1];
            float v00 = acc[mi][ni][0] + b0, v01 = acc[mi][ni][1] + b1;
            float v10 = acc[mi][ni][2] + b0, v11 = acc[mi][ni][3] + b1;
            if (OUT == 1) {
                v00 = fast_sigmoid(v00); v01 = fast_sigmoid(v01);
                v10 = fast_sigmoid(v10); v11 = fast_sigmoid(v11);
                *reinterpret_cast<float2*>(G + (size_t)m0 * HID + n0)       = make_float2(v00, v01);
                *reinterpret_cast<float2*>(G + (size_t)(m0 + 8) * HID + n0) = make_float2(v10, v11);
            } else {
                __nv_bfloat16 h0, l0, h1, l1;
                split_bf16(v00, h0, l0); split_bf16(v01, h1, l1);
                *reinterpret_cast<__nv_bfloat162*>(Chi + (size_t)m0 * HID + n0) = __nv_bfloat162(h0, h1);
                *reinterpret_cast<__nv_bfloat162*>(Clo + (size_t)m0 * HID + n0) = __nv_bfloat162(l0, l1);
                split_bf16(v10, h0, l0); split_bf16(v11, h1, l1);
                *reinterpret_cast<__nv_bfloat162*>(Chi + (size_t)(m0 + 8) * HID + n0) = __nv_bfloat162(h0, h1);
                *reinterpret_cast<__nv_bfloat162*>(Clo + (size_t)(m0 + 8) * HID + n0) = __nv_bfloat162(l0, l1);
            }
        }
    }
}

// ---------------- sequential scan: 2 chains/thread, 4-buffer deep pipeline ---
// Statically named register buffers A/B/C/D (compile-time indices only — no
// local-memory demotion). Software pipeline period = 4*SU = 32 steps
// (2048 % 32 == 0): loads issue THREE SU-batches (~1200 cyc) before
// consumption, covering low-occupancy DRAM latency (~800 cyc).
// Chain per step: v = a*h + c; e = ex2(v); h = 1 - 2*rcp(1+e). Two
// independent chains interleave to cover MUFU latency.
#define SU 8

#define SCAN_LOAD(s0, A0, C0, A1, C1)                                          \
    do {                                                                        \
        _Pragma("unroll")                                                       \
        for (int u = 0; u < SU; u++) {                                          \
            const int t = t0 + dt * ((s0) + u);                                 \
            const int idx = base + t * HID;                                     \
            const __nv_bfloat162 hh = *reinterpret_cast<const __nv_bfloat162*>(xh + idx); \
            const __nv_bfloat162 ll = *reinterpret_cast<const __nv_bfloat162*>(xl + idx); \
            const float2 gg = *reinterpret_cast<const float2*>(gp + idx);       \
            const float x0 = __bfloat162float(hh.x) + __bfloat162float(ll.x);   \
            const float x1 = __bfloat162float(hh.y) + __bfloat162float(ll.y);   \
            A0[u] = K2LOG2E * x0 * gg.x;                                        \
            C0[u] = K2LOG2E * x0 * x0 * (1.0f - gg.x);                          \
            A1[u] = K2LOG2E * x1 * gg.y;                                        \
            C1[u] = K2LOG2E * x1 * x1 * (1.0f - gg.y);                          \
        }                                                                       \
    } while (0)

#define SCAN_STEP(s0, A0, C0, A1, C1)                                           \
    do {                                                                        \
        _Pragma("unroll")                                                       \
        for (int u = 0; u < SU; u++) {                                          \
            const float v0 = fmaf(A0[u], h0, C0[u]);                            \
            const float v1 = fmaf(A1[u], h1, C1[u]);                            \
            const float e0 = fast_ex2(v0);                                      \
            const float e1 = fast_ex2(v1);                                      \
            h0 = fmaf(-2.0f, fast_rcp(e0 + 1.0f), 1.0f);                        \
            h1 = fmaf(-2.0f, fast_rcp(e1 + 1.0f), 1.0f);                        \
            const int tt = t0 + dt * ((s0) + u);                                \
            if (OM == 0) {                                                      \
                __nv_bfloat16 hi0, lo0, hi1, lo1;                               \
                split_bf16(h0, hi0, lo0); split_bf16(h1, hi1, lo1);             \
                *reinterpret_cast<__nv_bfloat162*>(yh + base + tt * HID)        \
                    = __nv_bfloat162(hi0, hi1);                                 \
                *reinterpret_cast<__nv_bfloat162*>(yl + base + tt * HID)        \
                    = __nv_bfloat162(lo0, lo1);                                 \
            } else {                                                            \
                *reinterpret_cast<float2*>(outF + obase + (size_t)tt * (2 * HID)) \
                    = make_float2(h0, h1);                                      \
            }                                                                   \
        }                                                                       \
    } while (0)

template <int OM>
__global__ __launch_bounds__(64)
void scan_tc(const __nv_bfloat16* __restrict__ xAhi, const __nv_bfloat16* __restrict__ xAlo,
             const float* __restrict__ gA,
             const __nv_bfloat16* __restrict__ xBhi, const __nv_bfloat16* __restrict__ xBlo,
             const float* __restrict__ gB,
             __nv_bfloat16* __restrict__ yAhi, __nv_bfloat16* __restrict__ yAlo,
             __nv_bfloat16* __restrict__ yBhi, __nv_bfloat16* __restrict__ yBlo,
             float* __restrict__ outF,
             float* __restrict__ hA, float* __restrict__ hB)
{
    const int gid = blockIdx.x * 64 + threadIdx.x;   // 0..8191
    const int dir = gid >> 12;
    const int id  = gid & 4095;
    const int b = id >> 7;            // 0..31
    const int j = (id & 127) << 1;    // even j: chains j, j+1

    const __nv_bfloat16 *xh, *xl;
    const float* gp;
    __nv_bfloat16 *yh, *yl;
    float* hp;
    int t0, dt;
    if (dir == 0) { xh = xAhi; xl = xAlo; gp = gA; yh = yAhi; yl = yAlo;
                    hp = hA; t0 = 0;        dt =  1; }
    else          { xh = xBhi; xl = xBlo; gp = gB; yh = yBhi; yl = yBlo;
                    hp = hB; t0 = SEQL - 1; dt = -1; }

    const int base = b * SEQL * HID + j;
    const size_t obase = (size_t)b * SEQL * (2 * HID) + (size_t)dir * HID + j;

    // four statically named prefetch buffers (register-resident by construction)
    float a0A[SU], c0A[SU], a1A[SU], c1A[SU];
    float a0B[SU], c0B[SU], a1B[SU], c1B[SU];
    float a0C[SU], c0C[SU], a1C[SU], c1C[SU];
    float a0D[SU], c0D[SU], a1D[SU], c1D[SU];

    float h0 = 0.0f, h1 = 0.0f;

    // preamble: 3 batches in flight
    SCAN_LOAD(0,      a0A, c0A, a1A, c1A);
    SCAN_LOAD(SU,     a0B, c0B, a1B, c1B);
    SCAN_LOAD(2 * SU, a0C, c0C, a1C, c1C);

    for (int s0 = 0; s0 < SEQL; s0 += 4 * SU) {
        if (s0 + 3 * SU < SEQL) SCAN_LOAD(s0 + 3 * SU, a0D, c0D, a1D, c1D);
        SCAN_STEP(s0, a0A, c0A, a1A, c1A);
        if (s0 + 4 * SU < SEQL) SCAN_LOAD(s0 + 4 * SU, a0A, c0A, a1A, c1A);
        SCAN_STEP(s0 + SU, a0B, c0B, a1B, c1B);
        if (s0 + 5 * SU < SEQL) SCAN_LOAD(s0 + 5 * SU, a0B, c0B, a1B, c1B);
        SCAN_STEP(s0 + 2 * SU, a0C, c0C, a1C, c1C);
        if (s0 + 6 * SU < SEQL) SCAN_LOAD(s0 + 6 * SU, a0C, c0C, a1C, c1C);
        SCAN_STEP(s0 + 3 * SU, a0D, c0D, a1D, c1D);
    }
    *reinterpret_cast<float2*>(hp + (b << 8) + j) = make_float2(h0, h1);
}

// ---------------- launch ----------------
extern "C" void kernel_launch(void* const* d_in, const int* in_sizes, int n_in,
                              void* d_out, int out_size)
{
    const float* x    = (const float*)d_in[0];  // [32,2048,512]
    const float* W_fc = (const float*)d_in[1];  // [256,512]
    const float* b_fc = (const float*)d_in[2];  // [256]
    // d_in[3] (W1), d_in[4] (b1): mathematically dead (blending1 == identity)
    const float* W2   = (const float*)d_in[5];  // [2,256,256]
    const float* b2   = (const float*)d_in[6];  // [2,256]
    float* out = (float*)d_out;

    __nv_bfloat16 *xhi, *xlo, *Wfc3, *W23, *Hhi, *Hlo, *Ylhi, *Yllo, *Yrhi, *Yrlo;
    float *G1, *Ga, *Gb, *hd;
    cudaGetSymbolAddress((void**)&xhi,  g_xhi);
    cudaGetSymbolAddress((void**)&xlo,  g_xlo);
    cudaGetSymbolAddress((void**)&Wfc3, g_Wfc3);
    cudaGetSymbolAddress((void**)&W23,  g_W23);
    cudaGetSymbolAddress((void**)&Hhi,  g_Hhi);
    cudaGetSymbolAddress((void**)&Hlo,  g_Hlo);
    cudaGetSymbolAddress((void**)&G1,   g_G1);
    cudaGetSymbolAddress((void**)&Ylhi, g_Ylhi);
    cudaGetSymbolAddress((void**)&Yllo, g_Yllo);
    cudaGetSymbolAddress((void**)&Yrhi, g_Yrhi);
    cudaGetSymbolAddress((void**)&Yrlo, g_Yrlo);
    cudaGetSymbolAddress((void**)&Ga,   g_Ga);
    cudaGetSymbolAddress((void**)&Gb,   g_Gb);
    cudaGetSymbolAddress((void**)&hd,   g_hdump);

    float* hout = (out_size >= XXN + HOUTN) ? (out + XXN) : hd;

    // 0) operand conversion (x -> hi/lo planes; W -> [Whi|Whi|Wlo])
    {
        int n4 = MTOT * INF / 4;
        convert_x_kernel<<<(n4 + 255) / 256, 256>>>(x, xhi, xlo, n4);
        int nw = HID * INF + 2 * HID * HID;
        convert_w_kernel<<<(nw + 255) / 256, 256>>>(W_fc, W2, Wfc3, W23);
    }

    const dim3 blk(256);
    const dim3 grd1(HID / 64, MTOT / 128, 1);   // bn fastest -> A reuse in L2
    const dim3 grd2(HID / 64, MTOT / 128, 2);

    // 1) input projection -> split bf16 H planes
    gemm_tc<0><<<grd1, blk>>>(xhi, xlo, nullptr, nullptr, Wfc3, b_fc,
                              nullptr, nullptr, Hhi, Hlo, INF);
    // 2) layer-1 gates (shared by both directions) -> fp32 G1
    gemm_tc<1><<<grd1, blk>>>(Hhi, Hlo, nullptr, nullptr, W23, b2,
                              G1, nullptr, nullptr, nullptr, HID);
    // 3) layer-1 scans (fwd+rev in one launch) -> split Y planes + h_out[0,1]
    scan_tc<0><<<128, 64>>>(Hhi, Hlo, G1, Hhi, Hlo, G1,
                            Ylhi, Yllo, Yrhi, Yrlo,
                            nullptr, hout, hout + BSZ * HID);
    // 4) layer-2 gates, both directions fused via gridDim.z -> Ga, Gb
    gemm_tc<1><<<grd2, blk>>>(Ylhi, Yllo, Yrhi, Yrlo,
                              W23 + (size_t)HID * 3 * HID, b2 + HID,
                              Ga, Gb, nullptr, nullptr, HID);
    // 5) layer-2 scans write straight into d_out + h_out[2,3]
    scan_tc<1><<<128, 64>>>(Ylhi, Yllo, Ga, Yrhi, Yrlo, Gb,
                            nullptr, nullptr, nullptr, nullptr,
                            out, hout + 2 * BSZ * HID, hout + 3 * BSZ * HID);
}

// round 14
// speedup vs baseline: 2.0157x; 1.3501x over previous
#include <cuda_runtime.h>
#include <cuda_bf16.h>
#include <math.h>
#include <stdint.h>

#define BSZ 32
#define SEQL 2048
#define INF 512
#define HID 256
#define MTOT (BSZ * SEQL)           // 65536 rows
#define XXN (BSZ * SEQL * 2 * HID)  // 33554432
#define HOUTN (4 * BSZ * HID)       // 32768

// ---------------- scratch (static device globals; no allocation) -------------
__device__ __nv_bfloat16 g_xhi [MTOT * INF];
__device__ __nv_bfloat16 g_xlo [MTOT * INF];
__device__ __nv_bfloat16 g_Wfc3[HID * 3 * INF];       // [Whi|Whi|Wlo] along k'
__device__ __nv_bfloat16 g_W23 [2 * HID * 3 * HID];
__device__ __nv_bfloat16 g_Hhi [MTOT * HID];
__device__ __nv_bfloat16 g_Hlo [MTOT * HID];
__device__ float         g_G1  [MTOT * HID];
__device__ __nv_bfloat16 g_Ylhi[MTOT * HID];
__device__ __nv_bfloat16 g_Yllo[MTOT * HID];
__device__ __nv_bfloat16 g_Yrhi[MTOT * HID];
__device__ __nv_bfloat16 g_Yrlo[MTOT * HID];
__device__ float         g_Ga  [MTOT * HID];
__device__ float         g_Gb  [MTOT * HID];
__device__ float         g_hdump[4 * BSZ * HID];

#define K2LOG2E 2.8853900817779268f   // 2*log2(e)

// ---------------- fast math ----------------
__device__ __forceinline__ float fast_ex2(float x) {
    float y; asm("ex2.approx.f32 %0, %1;" : "=f"(y) : "f"(x)); return y;
}
__device__ __forceinline__ float fast_rcp(float x) {
    float y; asm("rcp.approx.f32 %0, %1;" : "=f"(y) : "f"(x)); return y;
}
__device__ __forceinline__ float fast_sigmoid(float z) {
    return fast_rcp(1.0f + fast_ex2(-1.4426950408889634f * z));
}
__device__ __forceinline__ void split_bf16(float v, __nv_bfloat16& hi, __nv_bfloat16& lo) {
    hi = __float2bfloat16(v);
    lo = __float2bfloat16(v - __bfloat162float(hi));
}
// bf16 halves of a packed u32 -> f32 (shift trick: bf16 is top 16 bits of f32)
__device__ __forceinline__ float bf_lo(uint32_t r) { return __uint_as_float(r << 16); }
__device__ __forceinline__ float bf_hi(uint32_t r) { return __uint_as_float(r & 0xFFFF0000u); }

// ---------------- PTX helpers ----------------
__device__ __forceinline__ void ldsm4(uint32_t (&r)[4], uint32_t saddr) {
    asm volatile("ldmatrix.sync.aligned.m8n8.x4.shared.b16 {%0,%1,%2,%3}, [%4];"
                 : "=r"(r[0]), "=r"(r[1]), "=r"(r[2]), "=r"(r[3]) : "r"(saddr));
}
__device__ __forceinline__ void mma16816(float (&d)[4], const uint32_t (&a)[4],
                                         uint32_t b0, uint32_t b1) {
    asm volatile("mma.sync.aligned.m16n8k16.row.col.f32.bf16.bf16.f32 "
                 "{%0,%1,%2,%3}, {%4,%5,%6,%7}, {%8,%9}, {%0,%1,%2,%3};"
                 : "+f"(d[0]), "+f"(d[1]), "+f"(d[2]), "+f"(d[3])
                 : "r"(a[0]), "r"(a[1]), "r"(a[2]), "r"(a[3]), "r"(b0), "r"(b1));
}
__device__ __forceinline__ void cpa16(uint32_t s, const void* g) {
    asm volatile("cp.async.cg.shared.global [%0], [%1], 16;" :: "r"(s), "l"(g));
}
__device__ __forceinline__ void cpa4(uint32_t s, const void* g) {
    asm volatile("cp.async.ca.shared.global [%0], [%1], 4;" :: "r"(s), "l"(g));
}
__device__ __forceinline__ void cpa8(uint32_t s, const void* g) {
    asm volatile("cp.async.ca.shared.global [%0], [%1], 8;" :: "r"(s), "l"(g));
}
__device__ __forceinline__ void cpa_commit() { asm volatile("cp.async.commit_group;"); }

// ---------------- conversion kernels ----------------
__global__ void convert_x_kernel(const float* __restrict__ x,
                                 __nv_bfloat16* __restrict__ xhi,
                                 __nv_bfloat16* __restrict__ xlo, int n4)
{
    int i = blockIdx.x * blockDim.x + threadIdx.x;
    if (i >= n4) return;
    float4 v = reinterpret_cast<const float4*>(x)[i];
    __nv_bfloat16 h0, l0, h1, l1, h2, l2, h3, l3;
    split_bf16(v.x, h0, l0); split_bf16(v.y, h1, l1);
    split_bf16(v.z, h2, l2); split_bf16(v.w, h3, l3);
    reinterpret_cast<__nv_bfloat162*>(xhi)[2 * i]     = __nv_bfloat162(h0, h1);
    reinterpret_cast<__nv_bfloat162*>(xhi)[2 * i + 1] = __nv_bfloat162(h2, h3);
    reinterpret_cast<__nv_bfloat162*>(xlo)[2 * i]     = __nv_bfloat162(l0, l1);
    reinterpret_cast<__nv_bfloat162*>(xlo)[2 * i + 1] = __nv_bfloat162(l2, l3);
}

// Build W' = [Whi | Whi | Wlo] (k' = 3K) for W_fc and both W2 layers.
__global__ void convert_w_kernel(const float* __restrict__ Wfc,
                                 const float* __restrict__ W2,
                                 __nv_bfloat16* __restrict__ Wfc3,
                                 __nv_bfloat16* __restrict__ W23)
{
    int i = blockIdx.x * blockDim.x + threadIdx.x;
    const int t1 = HID * INF;
    const int t2 = 2 * HID * HID;
    if (i < t1) {
        int n = i / INF, k = i % INF;
        __nv_bfloat16 hi, lo; split_bf16(Wfc[i], hi, lo);
        __nv_bfloat16* base = Wfc3 + (size_t)n * (3 * INF);
        base[k] = hi; base[INF + k] = hi; base[2 * INF + k] = lo;
    } else if (i < t1 + t2) {
        int j = i - t1;
        int l = j / (HID * HID); int r = j % (HID * HID);
        int n = r / HID, k = r % HID;
        __nv_bfloat16 hi, lo; split_bf16(W2[j], hi, lo);
        __nv_bfloat16* base = W23 + (size_t)l * HID * (3 * HID) + (size_t)n * (3 * HID);
        base[k] = hi; base[HID + k] = hi; base[2 * HID + k] = lo;
    }
}

// ---------------- tensor-core GEMM (unchanged from R11 — proven) -------------
// Block tile 128x64, 8 warps (32x32 each), k-chunk 32, 3-stage cp.async
// circular pipeline, ONE __syncthreads per chunk, ldsm/mma fragment
// double-buffering. Grid: (N/64, M/128, nz) — bn fastest for A reuse in L2.
// OUT=0: C = A@W'^T + bias -> split bf16 planes Chi/Clo.
// OUT=1: g = sigmoid(acc + bias) -> fp32 G plane.
#define A_STRIDE 40
#define A_TILE (128 * A_STRIDE)
#define W_TILE (64 * A_STRIDE)
#define NSTG 3

template <int OUT>
__global__ __launch_bounds__(256, 2)
void gemm_tc(const __nv_bfloat16* __restrict__ Ahi_, const __nv_bfloat16* __restrict__ Alo_,
             const __nv_bfloat16* __restrict__ Ahi2, const __nv_bfloat16* __restrict__ Alo2,
             const __nv_bfloat16* __restrict__ W3, const float* __restrict__ bias,
             float* __restrict__ Ga, float* __restrict__ Gb,
             __nv_bfloat16* __restrict__ Chi, __nv_bfloat16* __restrict__ Clo, int K)
{
    __shared__ __nv_bfloat16 As[NSTG][A_TILE];
    __shared__ __nv_bfloat16 Ws[NSTG][W_TILE];

    const __nv_bfloat16* Ahi = (blockIdx.z == 0) ? Ahi_ : Ahi2;
    const __nv_bfloat16* Alo = (blockIdx.z == 0) ? Alo_ : Alo2;
    float* G = (blockIdx.z == 0) ? Ga : Gb;

    const int tid  = threadIdx.x;
    const int bm   = blockIdx.y * 128;
    const int bn   = blockIdx.x * 64;
    const int warp = tid >> 5;
    const int lane = tid & 31;
    const int K3   = 3 * K;
    const int n1   = K >> 5;
    const int nc   = 3 * n1;

    const uint32_t sA = (uint32_t)__cvta_generic_to_shared(&As[0][0]);
    const uint32_t sW = (uint32_t)__cvta_generic_to_shared(&Ws[0][0]);

    const int ar0 = tid >> 2, ar1 = (tid + 256) >> 2;
    const int ac  = (tid & 3) * 8;
    const int wr  = tid >> 2;
    const uint32_t sAoff0 = (uint32_t)(ar0 * A_STRIDE + ac) * 2;
    const uint32_t sAoff1 = (uint32_t)(ar1 * A_STRIDE + ac) * 2;
    const uint32_t sWoff  = (uint32_t)(wr  * A_STRIDE + ac) * 2;
    const __nv_bfloat16* Wg = W3 + (size_t)(bn + wr) * K3 + ac;

    float acc[2][4][4];
#pragma unroll
    for (int a = 0; a < 2; a++)
#pragma unroll
        for (int b = 0; b < 4; b++)
#pragma unroll
            for (int c = 0; c < 4; c++) acc[a][b][c] = 0.0f;

    auto prefetch = [&](int c, int buf) {
        const __nv_bfloat16* Aseg; int kk;
        if (c < n1)           { Aseg = Ahi; kk = c; }
        else if (c < 2 * n1)  { Aseg = Alo; kk = c - n1; }
        else                  { Aseg = Ahi; kk = c - 2 * n1; }
        const __nv_bfloat16* Abase = Aseg + (size_t)bm * K + kk * 32 + ac;
        cpa16(sA + buf * (A_TILE * 2) + sAoff0, Abase + (size_t)ar0 * K);
        cpa16(sA + buf * (A_TILE * 2) + sAoff1, Abase + (size_t)ar1 * K);
        cpa16(sW + buf * (W_TILE * 2) + sWoff,  Wg + c * 32);
    };

    const int wm = warp & 3;
    const int wn = warp >> 2;
    const int aRow = wm * 32 + (lane & 15);
    const int aColB = (lane >> 4) * 8;
    const int bRow = wn * 32 + (lane & 7) + ((lane >> 4) & 1) * 8;
    const int bColB = ((lane >> 3) & 1) * 8;

    uint32_t afr[2][2][4], bfr[2][2][4];

    auto load_frags = [&](int buf, int ks, int slot) {
        const uint32_t aBase = sA + buf * (A_TILE * 2);
        const uint32_t wBase = sW + buf * (W_TILE * 2);
#pragma unroll
        for (int mi = 0; mi < 2; mi++)
            ldsm4(afr[slot][mi], aBase + (uint32_t)((aRow + mi * 16) * A_STRIDE
                                                    + ks * 16 + aColB) * 2);
#pragma unroll
        for (int bi = 0; bi < 2; bi++)
            ldsm4(bfr[slot][bi], wBase + (uint32_t)((bRow + bi * 16) * A_STRIDE
                                                    + ks * 16 + bColB) * 2);
    };
    auto do_mma = [&](int slot) {
#pragma unroll
        for (int mi = 0; mi < 2; mi++) {
            mma16816(acc[mi][0], afr[slot][mi], bfr[slot][0][0], bfr[slot][0][1]);
            mma16816(acc[mi][1], afr[slot][mi], bfr[slot][0][2], bfr[slot][0][3]);
            mma16816(acc[mi][2], afr[slot][mi], bfr[slot][1][0], bfr[slot][1][1]);
            mma16816(acc[mi][3], afr[slot][mi], bfr[slot][1][2], bfr[slot][1][3]);
        }
    };

    prefetch(0, 0); cpa_commit();
    prefetch(1, 1); cpa_commit();
    asm volatile("cp.async.wait_group 1;");
    __syncthreads();
    load_frags(0, 0, 0);

    int buf = 0;
    for (int c = 0; c < nc; c++) {
        load_frags(buf, 1, 1);
        do_mma(0);
        if (c + 2 < nc) {
            int pf = buf + 2; if (pf >= NSTG) pf -= NSTG;
            prefetch(c + 2, pf);
            cpa_commit();
            asm volatile("cp.async.wait_group 1;");
        } else {
            asm volatile("cp.async.wait_group 0;");
        }
        __syncthreads();
        const int nbuf = (buf + 1 == NSTG) ? 0 : buf + 1;
        if (c + 1 < nc) load_frags(nbuf, 0, 0);
        do_mma(1);
        buf = nbuf;
    }

    // epilogue
#pragma unroll
    for (int mi = 0; mi < 2; mi++) {
#pragma unroll
        for (int ni = 0; ni < 4; ni++) {
            const int m0 = bm + wm * 32 + mi * 16 + (lane >> 2);
            const int n0 = bn + wn * 32 + ni * 8 + (lane & 3) * 2;
            const float b0 = bias[n0], b1 = bias[n0 + 1];
            float v00 = acc[mi][ni][0] + b0, v01 = acc[mi][ni][1] + b1;
            float v10 = acc[mi][ni][2] + b0, v11 = acc[mi][ni][3] + b1;
            if (OUT == 1) {
                v00 = fast_sigmoid(v00); v01 = fast_sigmoid(v01);
                v10 = fast_sigmoid(v10); v11 = fast_sigmoid(v11);
                *reinterpret_cast<float2*>(G + (size_t)m0 * HID + n0)       = make_float2(v00, v01);
                *reinterpret_cast<float2*>(G + (size_t)(m0 + 8) * HID + n0) = make_float2(v10, v11);
            } else {
                __nv_bfloat16 h0, l0, h1, l1;
                split_bf16(v00, h0, l0); split_bf16(v01, h1, l1);
                *reinterpret_cast<__nv_bfloat162*>(Chi + (size_t)m0 * HID + n0) = __nv_bfloat162(h0, h1);
                *reinterpret_cast<__nv_bfloat162*>(Clo + (size_t)m0 * HID + n0) = __nv_bfloat162(l0, l1);
                split_bf16(v10, h0, l0); split_bf16(v11, h1, l1);
                *reinterpret_cast<__nv_bfloat162*>(Chi + (size_t)(m0 + 8) * HID + n0) = __nv_bfloat162(h0, h1);
                *reinterpret_cast<__nv_bfloat162*>(Clo + (size_t)(m0 + 8) * HID + n0) = __nv_bfloat162(l0, l1);
            }
        }
    }
}

// ---------------- sequential scan: cp.async smem staging, zero reg pressure --
// 2 chains/thread (MUFU latency pairing). Prefetch pipeline lives in SHARED
// memory via cp.async — in-flight data costs no registers, so depth is 6
// stages x 8 steps (~2000 cyc of memory-latency cover). Each thread reads
// only slots it wrote itself -> per-thread cp.async.wait_group ordering, no
// __syncthreads. Empty commit_groups in the tail keep the wait window valid.
// Record per (stage, step, thread) = 16B: [bf162 xhi | bf162 xlo | float2 g].
// Chain per step: v = a*h + c; e = ex2(v); h = 1 - 2*rcp(1+e),
// with a = K*x*g, c = K*x^2 - a*x.
#define SSU 8
#define SNST 6
#define SNB (SEQL / SSU)   // 256 batches

template <int OM>
__global__ __launch_bounds__(64)
void scan_tc(const __nv_bfloat16* __restrict__ xAhi, const __nv_bfloat16* __restrict__ xAlo,
             const float* __restrict__ gA,
             const __nv_bfloat16* __restrict__ xBhi, const __nv_bfloat16* __restrict__ xBlo,
             const float* __restrict__ gB,
             __nv_bfloat16* __restrict__ yAhi, __nv_bfloat16* __restrict__ yAlo,
             __nv_bfloat16* __restrict__ yBhi, __nv_bfloat16* __restrict__ yBlo,
             float* __restrict__ outF,
             float* __restrict__ hA, float* __restrict__ hB)
{
    __shared__ __align__(16) uint32_t sbuf[SNST * SSU * 64 * 4];   // 48 KB

    const int tid = threadIdx.x;
    const int gid = blockIdx.x * 64 + tid;           // 0..8191
    const int dir = gid >> 12;
    const int id  = gid & 4095;
    const int b = id >> 7;            // 0..31
    const int j = (id & 127) << 1;    // even j: chains j, j+1

    const __nv_bfloat16 *xh, *xl;
    const float* gp;
    __nv_bfloat16 *yh, *yl;
    float* hp;
    int t0, dt;
    if (dir == 0) { xh = xAhi; xl = xAlo; gp = gA; yh = yAhi; yl = yAlo;
                    hp = hA; t0 = 0;        dt =  1; }
    else          { xh = xBhi; xl = xBlo; gp = gB; yh = yBhi; yl = yBlo;
                    hp = hB; t0 = SEQL - 1; dt = -1; }

    const int base = b * SEQL * HID + j;
    const size_t obase = (size_t)b * SEQL * (2 * HID) + (size_t)dir * HID + j;

    const uint32_t sbase = (uint32_t)__cvta_generic_to_shared(&sbuf[0]);

    // issue one batch of SSU steps into smem stage (sidx % SNST)
    auto issue_stage = [&](int sidx) {
        const int st = sidx % SNST;
        const int s0 = sidx * SSU;
        const uint32_t stb = sbase + (uint32_t)(((st * SSU) * 64 + tid) * 16);
#pragma unroll
        for (int u = 0; u < SSU; u++) {
            const int t = t0 + dt * (s0 + u);
            const int idx = base + t * HID;
            const uint32_t sa = stb + (uint32_t)(u * 64 * 16);
            cpa4(sa,     xh + idx);
            cpa4(sa + 4, xl + idx);
            cpa8(sa + 8, gp + idx);
        }
        cpa_commit();
    };

    float h0 = 0.0f, h1 = 0.0f;

    // prologue: SNST-1 batches in flight
#pragma unroll
    for (int s = 0; s < SNST - 1; s++) issue_stage(s);

    for (int sidx = 0; sidx < SNB; sidx++) {
        if (sidx + SNST - 1 < SNB) issue_stage(sidx + SNST - 1);
        else cpa_commit();   // empty group keeps the wait window sliding
        asm volatile("cp.async.wait_group %0;" :: "n"(SNST - 1));

        const int st = sidx % SNST;
        const int s0 = sidx * SSU;
        const uint32_t stb = sbase + (uint32_t)(((st * SSU) * 64 + tid) * 16);
#pragma unroll
        for (int u = 0; u < SSU; u++) {
            uint32_t r0, r1, r2, r3;
            asm volatile("ld.shared.v4.b32 {%0,%1,%2,%3}, [%4];"
                         : "=r"(r0), "=r"(r1), "=r"(r2), "=r"(r3)
                         : "r"(stb + (uint32_t)(u * 64 * 16)));
            const float x0 = bf_lo(r0) + bf_lo(r1);
            const float x1 = bf_hi(r0) + bf_hi(r1);
            const float g0 = __uint_as_float(r2);
            const float g1 = __uint_as_float(r3);
            const float k0 = K2LOG2E * x0;
            const float k1 = K2LOG2E * x1;
            const float a0 = k0 * g0;
            const float a1 = k1 * g1;
            const float c0 = fmaf(-a0, x0, k0 * x0);
            const float c1 = fmaf(-a1, x1, k1 * x1);

            const float v0 = fmaf(a0, h0, c0);
            const float v1 = fmaf(a1, h1, c1);
            const float e0 = fast_ex2(v0);
            const float e1 = fast_ex2(v1);
            h0 = fmaf(-2.0f, fast_rcp(e0 + 1.0f), 1.0f);
            h1 = fmaf(-2.0f, fast_rcp(e1 + 1.0f), 1.0f);

            const int tt = t0 + dt * (s0 + u);
            if (OM == 0) {
                __nv_bfloat16 hi0, lo0, hi1, lo1;
                split_bf16(h0, hi0, lo0); split_bf16(h1, hi1, lo1);
                *reinterpret_cast<__nv_bfloat162*>(yh + base + tt * HID) = __nv_bfloat162(hi0, hi1);
                *reinterpret_cast<__nv_bfloat162*>(yl + base + tt * HID) = __nv_bfloat162(lo0, lo1);
            } else {
                *reinterpret_cast<float2*>(outF + obase + (size_t)tt * (2 * HID))
                    = make_float2(h0, h1);
            }
        }
    }
    *reinterpret_cast<float2*>(hp + (b << 8) + j) = make_float2(h0, h1);
}

// ---------------- launch ----------------
extern "C" void kernel_launch(void* const* d_in, const int* in_sizes, int n_in,
                              void* d_out, int out_size)
{
    const float* x    = (const float*)d_in[0];  // [32,2048,512]
    const float* W_fc = (const float*)d_in[1];  // [256,512]
    const float* b_fc = (const float*)d_in[2];  // [256]
    // d_in[3] (W1), d_in[4] (b1): mathematically dead (blending1 == identity)
    const float* W2   = (const float*)d_in[5];  // [2,256,256]
    const float* b2   = (const float*)d_in[6];  // [2,256]
    float* out = (float*)d_out;

    __nv_bfloat16 *xhi, *xlo, *Wfc3, *W23, *Hhi, *Hlo, *Ylhi, *Yllo, *Yrhi, *Yrlo;
    float *G1, *Ga, *Gb, *hd;
    cudaGetSymbolAddress((void**)&xhi,  g_xhi);
    cudaGetSymbolAddress((void**)&xlo,  g_xlo);
    cudaGetSymbolAddress((void**)&Wfc3, g_Wfc3);
    cudaGetSymbolAddress((void**)&W23,  g_W23);
    cudaGetSymbolAddress((void**)&Hhi,  g_Hhi);
    cudaGetSymbolAddress((void**)&Hlo,  g_Hlo);
    cudaGetSymbolAddress((void**)&G1,   g_G1);
    cudaGetSymbolAddress((void**)&Ylhi, g_Ylhi);
    cudaGetSymbolAddress((void**)&Yllo, g_Yllo);
    cudaGetSymbolAddress((void**)&Yrhi, g_Yrhi);
    cudaGetSymbolAddress((void**)&Yrlo, g_Yrlo);
    cudaGetSymbolAddress((void**)&Ga,   g_Ga);
    cudaGetSymbolAddress((void**)&Gb,   g_Gb);
    cudaGetSymbolAddress((void**)&hd,   g_hdump);

    float* hout = (out_size >= XXN + HOUTN) ? (out + XXN) : hd;

    // 0) operand conversion (x -> hi/lo planes; W -> [Whi|Whi|Wlo])
    {
        int n4 = MTOT * INF / 4;
        convert_x_kernel<<<(n4 + 255) / 256, 256>>>(x, xhi, xlo, n4);
        int nw = HID * INF + 2 * HID * HID;
        convert_w_kernel<<<(nw + 255) / 256, 256>>>(W_fc, W2, Wfc3, W23);
    }

    const dim3 blk(256);
    const dim3 grd1(HID / 64, MTOT / 128, 1);   // bn fastest -> A reuse in L2
    const dim3 grd2(HID / 64, MTOT / 128, 2);

    // 1) input projection -> split bf16 H planes
    gemm_tc<0><<<grd1, blk>>>(xhi, xlo, nullptr, nullptr, Wfc3, b_fc,
                              nullptr, nullptr, Hhi, Hlo, INF);
    // 2) layer-1 gates (shared by both directions) -> fp32 G1
    gemm_tc<1><<<grd1, blk>>>(Hhi, Hlo, nullptr, nullptr, W23, b2,
                              G1, nullptr, nullptr, nullptr, HID);
    // 3) layer-1 scans (fwd+rev in one launch) -> split Y planes + h_out[0,1]
    scan_tc<0><<<128, 64>>>(Hhi, Hlo, G1, Hhi, Hlo, G1,
                            Ylhi, Yllo, Yrhi, Yrlo,
                            nullptr, hout, hout + BSZ * HID);
    // 4) layer-2 gates, both directions fused via gridDim.z -> Ga, Gb
    gemm_tc<1><<<grd2, blk>>>(Ylhi, Yllo, Yrhi, Yrlo,
                              W23 + (size_t)HID * 3 * HID, b2 + HID,
                              Ga, Gb, nullptr, nullptr, HID);
    // 5) layer-2 scans write straight into d_out + h_out[2,3]
    scan_tc<1><<<128, 64>>>(Ylhi, Yllo, Ga, Yrhi, Yrlo, Gb,
                            nullptr, nullptr, nullptr, nullptr,
                            out, hout + 2 * BSZ * HID, hout + 3 * BSZ * HID);
}